// round 14
// baseline (speedup 1.0000x reference)
#include <cuda_runtime.h>
#include <cuda_bf16.h>
#include <math.h>

#define Bb   2
#define Ll   4096
#define Dd   1024
#define Hh   4
#define CSs  32
#define NCc  128
#define BL   (Bb*Ll)
#define HD   1024
#define GIN  1792
#define GHID 1024
#define CH8  (8*NCc*8192)

// ---------------- scratch ----------------
__device__ float g_xqkv[BL*3072];
__device__ float g_q [BL*HD];
__device__ float g_k [BL*HD];
__device__ float g_v [BL*HD];
__device__ float g_u [CH8];
__device__ float g_delta[BL*HD];
__device__ float g_short[BL*HD];
__device__ float g_long [BL*HD];
__device__ float g_plg[4*BL*4];
__device__ float g_beta[BL*Hh];

__device__ __align__(16) __nv_bfloat16 g_hsH[BL*Dd];
__device__ __align__(16) __nv_bfloat16 g_hsL[BL*Dd];
__device__ __align__(16) __nv_bfloat16 g_ginH[BL*GIN];
__device__ __align__(16) __nv_bfloat16 g_ginL[BL*GIN];
__device__ __align__(16) __nv_bfloat16 g_ocH[BL*HD];
__device__ __align__(16) __nv_bfloat16 g_ocL[BL*HD];
#define WOFF_Q  0
#define WOFF_K  (1024*1024)
#define WOFF_V  (2*1024*1024)
#define WOFF_W1 (3*1024*1024)
#define WOFF_O  (3*1024*1024 + 1792*1024)
#define WTOT    (WOFF_O + 1024*1024)
__device__ __align__(16) __nv_bfloat16 g_wtH[WTOT];
__device__ __align__(16) __nv_bfloat16 g_wtL[WTOT];

// scan operand planes
__device__ __align__(16) __nv_bfloat16 g_qh[CH8], g_ql[CH8], g_wh[CH8], g_wl[CH8], g_kh[CH8], g_kl[CH8];
__device__ __align__(16) __nv_bfloat16 g_ah[8*NCc*1024], g_al[8*NCc*1024];

// ---------------- helpers ----------------
__device__ __forceinline__ float siluf(float x){ return x / (1.f + expf(-x)); }
__device__ __forceinline__ float geluf(float x){ return 0.5f * x * (1.f + erff(x * 0.70710678118654752f)); }
__device__ __forceinline__ void ldsm4(unsigned* r, unsigned addr){
    asm volatile("ldmatrix.sync.aligned.m8n8.x4.shared.b16 {%0,%1,%2,%3}, [%4];"
        : "=r"(r[0]),"=r"(r[1]),"=r"(r[2]),"=r"(r[3]) : "r"(addr));
}
__device__ __forceinline__ void ldsm4t(unsigned* r, unsigned addr){
    asm volatile("ldmatrix.sync.aligned.m8n8.x4.trans.shared.b16 {%0,%1,%2,%3}, [%4];"
        : "=r"(r[0]),"=r"(r[1]),"=r"(r[2]),"=r"(r[3]) : "r"(addr));
}
__device__ __forceinline__ void ldsm2(unsigned* r, unsigned addr){
    asm volatile("ldmatrix.sync.aligned.m8n8.x2.shared.b16 {%0,%1}, [%2];"
        : "=r"(r[0]),"=r"(r[1]) : "r"(addr));
}
__device__ __forceinline__ void mma16816(float* c, const unsigned* a, const unsigned* b){
    asm volatile("mma.sync.aligned.m16n8k16.row.col.f32.bf16.bf16.f32 "
        "{%0,%1,%2,%3}, {%4,%5,%6,%7}, {%8,%9}, {%0,%1,%2,%3};"
        : "+f"(c[0]),"+f"(c[1]),"+f"(c[2]),"+f"(c[3])
        : "r"(a[0]),"r"(a[1]),"r"(a[2]),"r"(a[3]), "r"(b[0]),"r"(b[1]));
}
__device__ __forceinline__ void cpa16(unsigned d, const void* s){
    asm volatile("cp.async.cg.shared.global [%0],[%1],16;\n" :: "r"(d), "l"(s));
}
#define CP_COMMIT() asm volatile("cp.async.commit_group;\n")
#define CP_WAIT0()  asm volatile("cp.async.wait_group 0;\n")
__device__ __forceinline__ unsigned pack2(float a, float b){
    __nv_bfloat162 t; t.x=__float2bfloat16(a); t.y=__float2bfloat16(b);
    return *(unsigned*)&t;
}
__device__ __forceinline__ float res1(float v){ return v - __bfloat162float(__float2bfloat16(v)); }
__device__ __forceinline__ void split1(float v, __nv_bfloat16& h, __nv_bfloat16& l){
    h = __float2bfloat16(v); l = __float2bfloat16(v - __bfloat162float(h));
}

// ---------------- fp32 -> (hi,lo) bf16 split ----------------
__global__ void split_kernel(const float4* __restrict__ x, uint2* __restrict__ hi,
                             uint2* __restrict__ lo, int n4)
{
    int i = blockIdx.x*blockDim.x + threadIdx.x;
    if (i >= n4) return;
    float4 v = x[i];
    uint2 ho, loo;
    ho.x = pack2(v.x, v.y);  ho.y = pack2(v.z, v.w);
    loo.x = pack2(res1(v.x), res1(v.y)); loo.y = pack2(res1(v.z), res1(v.w));
    hi[i] = ho; lo[i] = loo;
}

// ---------------- merged weight split ----------------
#define W4_Q  262144
#define W4_K  524288
#define W4_V  786432
#define W4_W1 1245184
#define W4_O  1507328
__global__ void wsplit_kernel(const float4* __restrict__ qw, const float4* __restrict__ kw,
                              const float4* __restrict__ vw, const float4* __restrict__ w1,
                              const float4* __restrict__ ow,
                              uint2* __restrict__ hi, uint2* __restrict__ lo)
{
    int i = blockIdx.x*blockDim.x + threadIdx.x;
    if (i >= W4_O) return;
    const float4* src; int local;
    if      (i < W4_Q)  { src = qw; local = i; }
    else if (i < W4_K)  { src = kw; local = i - W4_Q; }
    else if (i < W4_V)  { src = vw; local = i - W4_K; }
    else if (i < W4_W1) { src = w1; local = i - W4_V; }
    else                { src = ow; local = i - W4_W1; }
    float4 v = src[local];
    uint2 ho, loo;
    ho.x = pack2(v.x, v.y);  ho.y = pack2(v.z, v.w);
    loo.x = pack2(res1(v.x), res1(v.y)); loo.y = pack2(res1(v.z), res1(v.w));
    hi[i] = ho; lo[i] = loo;
}

// ---------------- bf16x3 split GEMM, 128x256 tile, 512 threads ----------
#define G2_STG   18432
#define G2_SMEM  (2*G2_STG*2)
template<int MODE>
__global__ void __launch_bounds__(512) hgemm_nt(const __nv_bfloat16* __restrict__ Ah,
                                                const __nv_bfloat16* __restrict__ Al,
                                                const __nv_bfloat16* __restrict__ Bh,
                                                const __nv_bfloat16* __restrict__ Bl,
                                                float* __restrict__ C,
                                                int M, int N, int K,
                                                const float* __restrict__ bias,
                                                const float* __restrict__ W2,
                                                float* __restrict__ PLG)
{
    extern __shared__ __align__(16) __nv_bfloat16 sm[];
    const int tid = threadIdx.x;
    const int bm = blockIdx.y*128, bn = blockIdx.x*256;
    const int warp = tid>>5, lane = tid&31;
    const int wm = warp>>3, wn = warp&7;
    float acc[4][4][4];
    #pragma unroll
    for (int i=0;i<4;i++) for(int j=0;j<4;j++) for(int r=0;r<4;r++) acc[i][j][r]=0.f;

    const bool doA = tid < 256;
    const size_t aoff = (size_t)(bm + ((tid & 255)>>1))*K + (tid&1)*8;
    const size_t boff = (size_t)(bn + (tid>>1))*K + (tid&1)*8;
    const int stoA = ((tid & 255)>>1)*24 + (tid&1)*8;
    const int stoB = 6144 + (tid>>1)*24 + (tid&1)*8;

    unsigned base = (unsigned)__cvta_generic_to_shared(sm);
    const int arow = wm*64 + (lane&15);
    const int acol = (lane>>4)*8;
    const int brow = wn*32 + ((lane>>4)&1)*8 + (lane&7);
    const int bcol = ((lane>>3)&1)*8;
    const int nk = K >> 4;

    {
        uint4 rAh, rAl;
        if (doA) { rAh = *(const uint4*)(Ah + aoff); rAl = *(const uint4*)(Al + aoff); }
        uint4 rBh = *(const uint4*)(Bh + boff);
        uint4 rBl = *(const uint4*)(Bl + boff);
        if (doA) {
            *(uint4*)(sm + stoA) = rAh;
            *(uint4*)(sm + 3072 + stoA) = rAl;
        }
        *(uint4*)(sm + stoB) = rBh;
        *(uint4*)(sm + 6144 + stoB) = rBl;
    }
    __syncthreads();

    for (int kt = 0; kt < nk; ++kt) {
        const int cur = kt & 1;
        const unsigned sb = base + (unsigned)cur*(G2_STG*2);
        uint4 nAh, nAl, nBh, nBl;
        const bool more = (kt + 1 < nk);
        if (more) {
            const size_t kb = boff + (size_t)(kt+1)*16;
            nBh = *(const uint4*)(Bh + kb);
            nBl = *(const uint4*)(Bl + kb);
            if (doA) {
                const size_t ka = aoff + (size_t)(kt+1)*16;
                nAh = *(const uint4*)(Ah + ka);
                nAl = *(const uint4*)(Al + ka);
            }
        }
        unsigned bh[4][2], bl[4][2];
        #pragma unroll
        for (int ng = 0; ng < 2; ++ng) {
            unsigned r4[4];
            ldsm4(r4, sb + 2u*(6144 + (brow + ng*16)*24 + bcol));
            bh[2*ng][0]=r4[0]; bh[2*ng][1]=r4[1]; bh[2*ng+1][0]=r4[2]; bh[2*ng+1][1]=r4[3];
            ldsm4(r4, sb + 2u*(12288 + (brow + ng*16)*24 + bcol));
            bl[2*ng][0]=r4[0]; bl[2*ng][1]=r4[1]; bl[2*ng+1][0]=r4[2]; bl[2*ng+1][1]=r4[3];
        }
        #pragma unroll
        for (int mt = 0; mt < 4; ++mt) {
            unsigned ah[4], al[4];
            ldsm4(ah, sb + 2u*((arow + mt*16)*24 + acol));
            ldsm4(al, sb + 2u*(3072 + (arow + mt*16)*24 + acol));
            #pragma unroll
            for (int nt = 0; nt < 4; ++nt) {
                mma16816(acc[mt][nt], ah, bh[nt]);
                mma16816(acc[mt][nt], ah, bl[nt]);
                mma16816(acc[mt][nt], al, bh[nt]);
            }
        }
        if (more) {
            __nv_bfloat16* d = sm + (cur^1)*G2_STG;
            if (doA) {
                *(uint4*)(d + stoA) = nAh;
                *(uint4*)(d + 3072 + stoA) = nAl;
            }
            *(uint4*)(d + stoB) = nBh;
            *(uint4*)(d + 6144 + stoB) = nBl;
            __syncthreads();
        }
    }
    const int g = lane>>2, tig = lane&3;
    if (MODE == 0) {
        #pragma unroll
        for (int mt = 0; mt < 4; ++mt) {
            const int row0 = bm + wm*64 + mt*16 + g;
            #pragma unroll
            for (int nt = 0; nt < 4; ++nt) {
                const int col = bn + wn*32 + nt*8 + tig*2;
                *(float2*)(C + (size_t)row0*N + col)     = make_float2(acc[mt][nt][0], acc[mt][nt][1]);
                *(float2*)(C + (size_t)(row0+8)*N + col) = make_float2(acc[mt][nt][2], acc[mt][nt][3]);
            }
        }
    } else {
        __syncthreads();
        float* slog = (float*)sm;
        #pragma unroll
        for (int mt = 0; mt < 4; ++mt) {
            #pragma unroll
            for (int half = 0; half < 2; ++half) {
                float pj[4] = {0.f, 0.f, 0.f, 0.f};
                const int rowL = wm*64 + mt*16 + g + half*8;
                #pragma unroll
                for (int nt = 0; nt < 4; ++nt) {
                    #pragma unroll
                    for (int rr = 0; rr < 2; ++rr) {
                        const int col = bn + wn*32 + nt*8 + tig*2 + rr;
                        const float v = geluf(acc[mt][nt][half*2+rr] + bias[col]);
                        #pragma unroll
                        for (int j = 0; j < 4; ++j)
                            pj[j] += v * W2[j*GHID + col];
                    }
                }
                #pragma unroll
                for (int j = 0; j < 4; ++j) {
                    float s = pj[j];
                    s += __shfl_xor_sync(0xffffffffu, s, 1);
                    s += __shfl_xor_sync(0xffffffffu, s, 2);
                    if (tig == 0) slog[wn*512 + rowL*4 + j] = s;
                }
            }
        }
        __syncthreads();
        if (tid < 512) {
            const int row = tid >> 2;
            float s = 0.f;
            #pragma unroll
            for (int w8 = 0; w8 < 8; ++w8) s += slog[w8*512 + tid];
            PLG[((size_t)blockIdx.x*BL + bm + row)*4 + (tid & 3)] = s;
        }
    }
}

// ---------------- beta ----------------
__global__ void beta_kernel(const float* __restrict__ hs, const float* __restrict__ bw,
                            float* __restrict__ beta)
{
    const int row = blockIdx.x;
    const int warp = threadIdx.x >> 5, lane = threadIdx.x & 31;
    const float* x = hs + (size_t)row * Dd;
    const float* w = bw + warp * Dd;
    float s = 0.f;
    for (int i = lane; i < Dd; i += 32) s += x[i] * w[i];
    #pragma unroll
    for (int o = 16; o; o >>= 1) s += __shfl_xor_sync(0xffffffff, s, o);
    if (lane == 0) beta[row*4 + warp] = 1.f / (1.f + expf(-s));
}

// ---------------- conv + silu + l2norm, 8 rows/block ----------------
#define CV_SMEM ((16384 + 64)*4)
__global__ void __launch_bounds__(256) conv_silu_norm(const float* __restrict__ XQKV,
                               const float* __restrict__ WQ, const float* __restrict__ WK,
                               const float* __restrict__ WV,
                               float* __restrict__ Qo, float* __restrict__ Ko,
                               float* __restrict__ Vo)
{
    extern __shared__ float cs[];
    float* sq = cs;
    float* sk = cs + 8192;
    float* red = cs + 16384;
    const int blk = blockIdx.x;
    const int b = blk / (Ll/8);
    const int l0 = (blk % (Ll/8)) * 8;
    const int tid = threadIdx.x;
    const int warp = tid>>5, lane = tid&31;
    if (tid < 64) red[tid] = 0.f;
    __syncthreads();

    #pragma unroll
    for (int j = 0; j < 4; ++j) {
        const int c = tid + 256*j;
        float win[11];
        #pragma unroll
        for (int t = 0; t < 11; ++t) {
            const int l = l0 - 3 + t;
            win[t] = (l >= 0) ? XQKV[((size_t)(b*Ll + l))*3072 + c] : 0.f;
        }
        {
            const float w0 = WQ[c*4+0], w1 = WQ[c*4+1], w2 = WQ[c*4+2], w3 = WQ[c*4+3];
            #pragma unroll
            for (int r = 0; r < 8; ++r)
                sq[r*1024 + c] = siluf(win[r]*w0 + win[r+1]*w1 + win[r+2]*w2 + win[r+3]*w3);
        }
        #pragma unroll
        for (int t = 0; t < 11; ++t) {
            const int l = l0 - 3 + t;
            win[t] = (l >= 0) ? XQKV[((size_t)(b*Ll + l))*3072 + 1024 + c] : 0.f;
        }
        {
            const float w0 = WK[c*4+0], w1 = WK[c*4+1], w2 = WK[c*4+2], w3 = WK[c*4+3];
            #pragma unroll
            for (int r = 0; r < 8; ++r)
                sk[r*1024 + c] = siluf(win[r]*w0 + win[r+1]*w1 + win[r+2]*w2 + win[r+3]*w3);
        }
        #pragma unroll
        for (int t = 0; t < 11; ++t) {
            const int l = l0 - 3 + t;
            win[t] = (l >= 0) ? XQKV[((size_t)(b*Ll + l))*3072 + 2048 + c] : 0.f;
        }
        {
            const float w0 = WV[c*4+0], w1 = WV[c*4+1], w2 = WV[c*4+2], w3 = WV[c*4+3];
            #pragma unroll
            for (int r = 0; r < 8; ++r)
                Vo[((size_t)(b*Ll + l0 + r))*HD + c] =
                    siluf(win[r]*w0 + win[r+1]*w1 + win[r+2]*w2 + win[r+3]*w3);
        }
    }
    __syncthreads();

    #pragma unroll
    for (int gi = 0; gi < 4; ++gi) {
        const int group = warp*4 + gi;
        const int r = group >> 2, h = group & 3;
        float sQ = 0.f, sK = 0.f;
        #pragma unroll
        for (int i = 0; i < 8; ++i) {
            const float vq = sq[r*1024 + h*256 + lane + 32*i];
            const float vk = sk[r*1024 + h*256 + lane + 32*i];
            sQ += vq*vq; sK += vk*vk;
        }
        #pragma unroll
        for (int o = 16; o; o >>= 1) {
            sQ += __shfl_xor_sync(0xffffffff, sQ, o);
            sK += __shfl_xor_sync(0xffffffff, sK, o);
        }
        if (lane == 0) { red[group] = rsqrtf(sQ + 1e-12f); red[32+group] = rsqrtf(sK + 1e-12f); }
    }
    __syncthreads();

    #pragma unroll
    for (int j = 0; j < 4; ++j) {
        const int c = tid + 256*j;
        #pragma unroll
        for (int r = 0; r < 8; ++r) {
            const size_t go = ((size_t)(b*Ll + l0 + r))*HD + c;
            Qo[go] = sq[r*1024 + c] * red[r*4 + j];
            Ko[go] = sk[r*1024 + c] * red[32 + r*4 + j];
        }
    }
}

// ---------------- precompute (tensor-core, beta folded into Tinv; 2 CTAs/SM) ---------
#define OQH 0
#define OQL 16896
#define OKH 33792
#define OKL 50688
#define OVH 67584
#define OVL 84480
#define OTH 101376
#define OTL 103936
#define OAM 106496
#define OTI 110720
#define OSB 114944
#define PRE_SMEM 115072

__global__ void __launch_bounds__(256) precompute_kernel(
    const float* __restrict__ Qn, const float* __restrict__ Kn,
    const float* __restrict__ V,  const float* __restrict__ beta,
    float* __restrict__ U,
    __nv_bfloat16* __restrict__ QH, __nv_bfloat16* __restrict__ QL,
    __nv_bfloat16* __restrict__ WH, __nv_bfloat16* __restrict__ WL,
    __nv_bfloat16* __restrict__ KH, __nv_bfloat16* __restrict__ KL,
    __nv_bfloat16* __restrict__ AH, __nv_bfloat16* __restrict__ AL)
{
    extern __shared__ char smraw[];
    const unsigned smb = (unsigned)__cvta_generic_to_shared(smraw);
    float* Amp = (float*)(smraw + OAM);
    float* Tip = (float*)(smraw + OTI);
    float* sbp = (float*)(smraw + OSB);
    const int idx = blockIdx.x;
    const int bh = idx >> 7, ci = idx & 127;
    const int b = bh >> 2, h = bh & 3;
    const int tid = threadIdx.x, warp = tid>>5, lane = tid&31;
    const int g = lane>>2, qp = (lane&3)*2;
    const size_t cb8 = (size_t)idx*8192;
    const size_t cb1 = (size_t)idx*1024;

    if (tid < 32) sbp[tid] = beta[(size_t)(b*Ll + ci*CSs + tid)*4 + h];
    __syncthreads();

    for (int e = tid; e < 8192; e += 256) {
        const int i = e >> 8, d = e & 255;
        const size_t gg = ((size_t)(b*Ll + ci*CSs + i))*HD + h*256 + d;
        const float qv = Qn[gg], kv = Kn[gg], vv = V[gg];
        __nv_bfloat16 hh, ll;
        split1(qv, hh, ll);
        *(__nv_bfloat16*)(smraw + OQH + (i*264+d)*2) = hh;
        *(__nv_bfloat16*)(smraw + OQL + (i*264+d)*2) = ll;
        QH[cb8+e] = hh; QL[cb8+e] = ll;
        split1(kv, hh, ll);
        *(__nv_bfloat16*)(smraw + OKH + (i*264+d)*2) = hh;
        *(__nv_bfloat16*)(smraw + OKL + (i*264+d)*2) = ll;
        split1(vv, hh, ll);
        *(__nv_bfloat16*)(smraw + OVH + (i*264+d)*2) = hh;
        *(__nv_bfloat16*)(smraw + OVL + (i*264+d)*2) = ll;
    }
    __syncthreads();

    {
        const int mt = warp>>2, ntw = warp&3;
        float qk[4] = {0,0,0,0}, kk[4] = {0,0,0,0};
        const unsigned arow_off = (mt*16 + (lane&15))*528 + ((lane>>4)*8)*2;
        const unsigned brow_off = (ntw*8 + (lane&7))*528 + (((lane>>3)&1)*8)*2;
        #pragma unroll
        for (int kt = 0; kt < 16; ++kt) {
            const unsigned kb2 = kt*32;
            unsigned aq[4], aql[4], ak4[4], akl[4], b2h[2], b2l[2];
            ldsm4(aq,  smb + OQH + arow_off + kb2);
            ldsm4(aql, smb + OQL + arow_off + kb2);
            ldsm4(ak4, smb + OKH + arow_off + kb2);
            ldsm4(akl, smb + OKL + arow_off + kb2);
            ldsm2(b2h, smb + OKH + brow_off + kb2);
            ldsm2(b2l, smb + OKL + brow_off + kb2);
            mma16816(qk, aq, b2h);  mma16816(qk, aql, b2h); mma16816(qk, aq, b2l);
            mma16816(kk, ak4, b2h); mma16816(kk, akl, b2h); mma16816(kk, ak4, b2l);
        }
        const int i0 = mt*16 + g, j0 = ntw*8 + qp;
        #pragma unroll
        for (int r = 0; r < 4; ++r) {
            const int i = i0 + (r>>1)*8, j = j0 + (r&1);
            Amp[i*33+j] = (i > j) ? sbp[i]*kk[r] : 0.f;
            const float av = (i >= j) ? qk[r] : 0.f;
            __nv_bfloat16 hh, ll;
            split1(av, hh, ll);
            AH[cb1 + i*32 + j] = hh; AL[cb1 + i*32 + j] = ll;
        }
    }
    for (int e = tid; e < 8192; e += 256) {
        const int d = e >> 5, t = e & 31;
        unsigned short hv = *(unsigned short*)(smraw + OKH + (t*264+d)*2) ^ 0x8000u;
        unsigned short lv = *(unsigned short*)(smraw + OKL + (t*264+d)*2) ^ 0x8000u;
        KH[cb8+e] = *(__nv_bfloat16*)&hv;
        KL[cb8+e] = *(__nv_bfloat16*)&lv;
    }
    __syncthreads();

    if (tid < 32) {
        const int j = tid;
        Tip[j] = (j == 0) ? 1.f : 0.f;
        for (int i2 = 1; i2 < 32; ++i2) {
            __syncwarp();
            float s = 0.f;
            for (int m = 0; m < i2; ++m) s += Amp[i2*33+m]*Tip[m*33+j];
            Tip[i2*33+j] = ((i2 == j) ? 1.f : 0.f) - s;
        }
    }
    __syncthreads();
    for (int e = tid; e < 1024; e += 256) {
        const int i = e >> 5, j = e & 31;
        __nv_bfloat16 hh, ll;
        split1(Tip[i*33+j] * sbp[j], hh, ll);
        *(__nv_bfloat16*)(smraw + OTH + (i*40+j)*2) = hh;
        *(__nv_bfloat16*)(smraw + OTL + (i*40+j)*2) = ll;
    }
    __syncthreads();

    {
        const int mt = warp>>2;
        unsigned TiH[2][4], TiL[2][4];
        #pragma unroll
        for (int kt = 0; kt < 2; ++kt) {
            const unsigned ao = (mt*16 + (lane&15))*80 + (kt*16 + (lane>>4)*8)*2;
            ldsm4(TiH[kt], smb + OTH + ao);
            ldsm4(TiL[kt], smb + OTL + ao);
        }
        const int i0 = mt*16 + g;
        #pragma unroll
        for (int ng = 0; ng < 4; ++ng) {
            const int n0 = (warp&3)*64 + ng*16;
            float aU[2][4], aW[2][4];
            #pragma unroll
            for (int t2 = 0; t2 < 2; ++t2)
                #pragma unroll
                for (int r = 0; r < 4; ++r) { aU[t2][r]=0.f; aW[t2][r]=0.f; }
            #pragma unroll
            for (int kt = 0; kt < 2; ++kt) {
                const unsigned brow = kt*16 + (lane&7) + ((lane>>3)&1)*8;
                const unsigned bcol = n0 + ((lane>>4)&1)*8;
                const unsigned bo = brow*528 + bcol*2;
                unsigned bvh[4], bvl[4], bbh[4], bbl[4];
                ldsm4t(bvh, smb + OVH + bo);
                ldsm4t(bvl, smb + OVL + bo);
                ldsm4t(bbh, smb + OKH + bo);
                ldsm4t(bbl, smb + OKL + bo);
                #pragma unroll
                for (int nt = 0; nt < 2; ++nt) {
                    mma16816(aU[nt], TiH[kt], bvh+2*nt);
                    mma16816(aU[nt], TiL[kt], bvh+2*nt);
                    mma16816(aU[nt], TiH[kt], bvl+2*nt);
                    mma16816(aW[nt], TiH[kt], bbh+2*nt);
                    mma16816(aW[nt], TiL[kt], bbh+2*nt);
                    mma16816(aW[nt], TiH[kt], bbl+2*nt);
                }
            }
            #pragma unroll
            for (int nt = 0; nt < 2; ++nt)
                #pragma unroll
                for (int r = 0; r < 4; ++r) {
                    const int i = i0 + (r>>1)*8;
                    const int d = n0 + nt*8 + qp + (r&1);
                    U[cb8 + i*256 + d] = aU[nt][r];
                    __nv_bfloat16 hh, ll;
                    split1(aW[nt][r], hh, ll);
                    WH[cb8 + i*256 + d] = hh;
                    WL[cb8 + i*256 + d] = ll;
                }
        }
    }
}

// ---------------- tensor-core delta scan (earlier prefetch) ----------------
#define STGSZ  72704
#define OFF_KT 145408
#define OFF_UB 210944
#define SC_SMEM 227840

__global__ void __launch_bounds__(128) scan_mma(
    const __nv_bfloat16* __restrict__ QHp, const __nv_bfloat16* __restrict__ QLp,
    const __nv_bfloat16* __restrict__ WHp, const __nv_bfloat16* __restrict__ WLp,
    const __nv_bfloat16* __restrict__ KHp, const __nv_bfloat16* __restrict__ KLp,
    const __nv_bfloat16* __restrict__ AHp, const __nv_bfloat16* __restrict__ ALp,
    const float* __restrict__ Ug, float* __restrict__ Out)
{
    extern __shared__ char smraw[];
    const unsigned smb = (unsigned)__cvta_generic_to_shared(smraw);
    float* ub = (float*)(smraw + OFF_UB);
    const int tid = threadIdx.x, warp = tid>>5, lane = tid&31;
    const int bh = blockIdx.x>>4, cb = blockIdx.x&15;
    const int b = bh>>2, h = bh&3;
    const int g = lane>>2, qp = (lane&3)*2;
    const int brow16 = ((lane>>4)&1)*8 + (lane&7);
    const int bcol8 = ((lane>>3)&1)*8;

    float P[8][4];
    #pragma unroll
    for (int i=0;i<8;++i)
        #pragma unroll
        for (int r=0;r<4;++r) P[i][r]=0.f;

    auto issue = [&](int ci, int stg){
        const size_t b8 = (size_t)(bh*NCc + ci)*8192;
        const size_t b1 = (size_t)(bh*NCc + ci)*1024;
        const unsigned sb = smb + stg*STGSZ;
        const __nv_bfloat16* srcs[4] = {QHp+b8, QLp+b8, WHp+b8, WLp+b8};
        #pragma unroll
        for (int pl = 0; pl < 4; ++pl){
            const unsigned dsb = sb + pl*16384;
            for (int e = tid; e < 1024; e += 128){
                int row = e>>5, c = e&31;
                cpa16(dsb + row*512 + ((c^(row&7))<<4), srcs[pl] + row*256 + c*8);
            }
        }
        const unsigned kb2 = smb + OFF_KT + stg*32768;
        for (int e = tid; e < 1024; e += 128){
            int row = e>>2, c = e&3;
            cpa16(kb2 + row*64 + c*16, KHp + b8 + row*32 + c*8);
            cpa16(kb2 + 16384 + row*64 + c*16, KLp + b8 + row*32 + c*8);
        }
        {
            int row = tid>>2, c = tid&3;
            cpa16(sb + 65536 + row*80 + c*16, AHp + b1 + row*32 + c*8);
            cpa16(sb + 68096 + row*80 + c*16, ALp + b1 + row*32 + c*8);
            cpa16(sb + 70656 + row*64 + c*16, Ug + b8 + (size_t)row*256 + cb*16 + c*4);
        }
    };

    issue(0, 0); CP_COMMIT();

    for (int ci = 0; ci < NCc; ++ci) {
        const int stg = ci & 1;
        const unsigned sb = smb + stg*STGSZ;
        const unsigned kb = smb + OFF_KT + stg*32768;
        CP_WAIT0();
        __syncthreads();
        // prefetch next chunk immediately: buffer stg^1 is free (all warps
        // finished the previous iteration's reads at the barrier above)
        if (ci + 1 < NCc) { issue(ci+1, stg^1); CP_COMMIT(); }

        float accW[4][4], accQ[4][4];
        #pragma unroll
        for (int i=0;i<4;++i)
            #pragma unroll
            for (int r=0;r<4;++r){ accW[i][r]=0.f; accQ[i][r]=0.f; }
        #pragma unroll
        for (int kt = 0; kt < 4; ++kt) {
            unsigned Ah[4], Al[4];
            const float* p0 = P[2*kt]; const float* p1 = P[2*kt+1];
            Ah[0]=pack2(p0[0],p0[1]); Ah[1]=pack2(p0[2],p0[3]);
            Ah[2]=pack2(p1[0],p1[1]); Ah[3]=pack2(p1[2],p1[3]);
            Al[0]=pack2(res1(p0[0]),res1(p0[1])); Al[1]=pack2(res1(p0[2]),res1(p0[3]));
            Al[2]=pack2(res1(p1[0]),res1(p1[1])); Al[3]=pack2(res1(p1[2]),res1(p1[3]));
            const int dcol = warp*64 + kt*16 + bcol8;
            unsigned bwh[4][2], bwl[4][2], bqh[4][2], bql[4][2];
            #pragma unroll
            for (int ng = 0; ng < 2; ++ng) {
                const int row = ng*16 + brow16;
                const unsigned off = row*512 + ((((unsigned)(dcol>>3))^(row&7))<<4);
                unsigned r4[4];
                ldsm4(r4, sb + 32768 + off);
                bwh[2*ng][0]=r4[0]; bwh[2*ng][1]=r4[1]; bwh[2*ng+1][0]=r4[2]; bwh[2*ng+1][1]=r4[3];
                ldsm4(r4, sb + 49152 + off);
                bwl[2*ng][0]=r4[0]; bwl[2*ng][1]=r4[1]; bwl[2*ng+1][0]=r4[2]; bwl[2*ng+1][1]=r4[3];
                ldsm4(r4, sb + off);
                bqh[2*ng][0]=r4[0]; bqh[2*ng][1]=r4[1]; bqh[2*ng+1][0]=r4[2]; bqh[2*ng+1][1]=r4[3];
                ldsm4(r4, sb + 16384 + off);
                bql[2*ng][0]=r4[0]; bql[2*ng][1]=r4[1]; bql[2*ng+1][0]=r4[2]; bql[2*ng+1][1]=r4[3];
            }
            #pragma unroll
            for (int nt = 0; nt < 4; ++nt) {
                mma16816(accW[nt], Ah, bwh[nt]);
                mma16816(accW[nt], Al, bwh[nt]);
                mma16816(accW[nt], Ah, bwl[nt]);
                mma16816(accQ[nt], Ah, bqh[nt]);
                mma16816(accQ[nt], Al, bqh[nt]);
                mma16816(accQ[nt], Ah, bql[nt]);
            }
        }
        #pragma unroll
        for (int nt = 0; nt < 4; ++nt)
            #pragma unroll
            for (int r = 0; r < 4; ++r) {
                int c = g + ((r>>1)<<3), t = nt*8 + qp + (r&1);
                ub[(c*4+warp)*66 + t] = accW[nt][r];
                ub[(c*4+warp)*66 + 32 + t] = accQ[nt][r];
            }
        __syncthreads();

        const float* su = (const float*)(smraw + stg*STGSZ + 70656);
        unsigned UH[2][4], UL[2][4];
        #pragma unroll
        for (int kt = 0; kt < 2; ++kt) {
            float v[8];
            #pragma unroll
            for (int p = 0; p < 8; ++p) {
                const int c = g + (((p>>1)&1)<<3);
                const int t = kt*16 + qp + (p&1) + ((p>>2)<<3);
                const int bi = (c*4)*66 + t;
                v[p] = su[t*16 + c] + ub[bi] + ub[bi+66] + ub[bi+132] + ub[bi+198];
            }
            UH[kt][0]=pack2(v[0],v[1]); UH[kt][1]=pack2(v[2],v[3]);
            UH[kt][2]=pack2(v[4],v[5]); UH[kt][3]=pack2(v[6],v[7]);
            UL[kt][0]=pack2(res1(v[0]),res1(v[1])); UL[kt][1]=pack2(res1(v[2]),res1(v[3]));
            UL[kt][2]=pack2(res1(v[4]),res1(v[5])); UL[kt][3]=pack2(res1(v[6]),res1(v[7]));
        }
        float oc[4];
        const int i0 = warp*8 + qp;
        #pragma unroll
        for (int r = 0; r < 4; ++r) {
            const int c = g + ((r>>1)<<3);
            const int bi = (c*4)*66 + 32 + i0 + (r&1);
            oc[r] = -(ub[bi] + ub[bi+66] + ub[bi+132] + ub[bi+198]);
        }

        #pragma unroll
        for (int kt = 0; kt < 2; ++kt) {
            unsigned bh2[2], bl2[2];
            const unsigned aoff = (warp*8 + (lane&7))*80 + (kt*16 + bcol8)*2;
            ldsm2(bh2, sb + 65536 + aoff);
            ldsm2(bl2, sb + 68096 + aoff);
            mma16816(oc, UH[kt], bh2);
            mma16816(oc, UL[kt], bh2);
            mma16816(oc, UH[kt], bl2);
        }
        {
            const size_t base = ((size_t)(b*Ll + ci*CSs + i0))*HD + h*256 + cb*16;
            Out[base + g]          = oc[0];
            Out[base + HD + g]     = oc[1];
            Out[base + g + 8]      = oc[2];
            Out[base + HD + g + 8] = oc[3];
        }

        #pragma unroll
        for (int kt = 0; kt < 2; ++kt) {
            #pragma unroll
            for (int np = 0; np < 4; ++np) {
                unsigned bh4[4], bl4[4];
                const unsigned off = (warp*64 + np*16 + brow16)*64 + (kt*16 + bcol8)*2;
                ldsm4(bh4, kb + off);
                ldsm4(bl4, kb + 16384 + off);
                mma16816(P[2*np],   UH[kt], bh4);
                mma16816(P[2*np],   UL[kt], bh4);
                mma16816(P[2*np],   UH[kt], bl4);
                mma16816(P[2*np+1], UH[kt], bh4+2);
                mma16816(P[2*np+1], UL[kt], bh4+2);
                mma16816(P[2*np+1], UH[kt], bl4+2);
            }
        }
    }
}

// ---------------- FIR short/long + gate_in, 16 rows/block, 1 CTA/SM regs ----------
__global__ void __launch_bounds__(256, 1) fir_gatein_kernel(
                                  const unsigned* __restrict__ hsHu, const unsigned* __restrict__ hsLu,
                                  const float* __restrict__ V,
                                  const float* __restrict__ ws, const float* __restrict__ wl,
                                  const float* __restrict__ Dl,
                                  float* __restrict__ Sout, float* __restrict__ Lout,
                                  __nv_bfloat16* __restrict__ GinH, __nv_bfloat16* __restrict__ GinL)
{
    const int blk = blockIdx.x;
    const int b = blk / (Ll/16);
    const int l0 = (blk % (Ll/16)) * 16;
    const int tid = threadIdx.x;
    float smean[16], lmean[16], dmean[16];
    #pragma unroll
    for (int r = 0; r < 16; ++r) { smean[r]=0.f; lmean[r]=0.f; dmean[r]=0.f; }
    for (int j = 0; j < 4; ++j) {
        const int ch = tid + 256*j;
        float win[46];
        #pragma unroll
        for (int t = 0; t < 46; ++t) {
            const int l = l0 - 30 + t;
            win[t] = (l >= 0) ? V[((size_t)(b*Ll + l))*HD + ch] : 0.f;
        }
        float wlr[31];
        #pragma unroll
        for (int t = 0; t < 31; ++t) wlr[t] = wl[ch*31 + t];
        const float w0 = ws[ch*3+0], w1 = ws[ch*3+1], w2 = ws[ch*3+2];
        #pragma unroll
        for (int r = 0; r < 16; ++r) {
            float yl = 0.f;
            #pragma unroll
            for (int t = 0; t < 31; ++t) yl += win[r+t]*wlr[t];
            const float ysv = win[r+28]*w0 + win[r+29]*w1 + win[r+30]*w2;
            const size_t row = (size_t)(b*Ll + l0 + r);
            Sout[row*HD + ch] = ysv;
            Lout[row*HD + ch] = yl;
            smean[r] += ysv; lmean[r] += yl;
            dmean[r] += Dl[row*HD + ch];
        }
    }
    for (int r = 0; r < 16; ++r) {
        const size_t row = (size_t)(b*Ll + l0 + r);
        __nv_bfloat16* gH = GinH + row*GIN;
        __nv_bfloat16* gL = GinL + row*GIN;
        #pragma unroll
        for (int j = 0; j < 2; ++j) {
            const int e = tid + 256*j;
            ((unsigned*)gH)[e] = hsHu[row*512 + e];
            ((unsigned*)gL)[e] = hsLu[row*512 + e];
        }
        __nv_bfloat16 hh, ll;
        split1(smean[r]*0.25f, hh, ll);
        gH[1024 + tid] = hh; gL[1024 + tid] = ll;
        split1(lmean[r]*0.25f, hh, ll);
        gH[1280 + tid] = hh; gL[1280 + tid] = ll;
        split1(dmean[r]*0.25f, hh, ll);
        gH[1536 + tid] = hh; gL[1536 + tid] = ll;
    }
}

// ---------------- combine + gate softmax + RMSNorm ----------------
__global__ void combine_kernel(const float* __restrict__ Sh, const float* __restrict__ Lg,
                               const float* __restrict__ Dl, const float* __restrict__ V,
                               const float* __restrict__ PLG, const float* __restrict__ b2,
                               const float* __restrict__ ltemp, const float* __restrict__ onw,
                               __nv_bfloat16* __restrict__ OH, __nv_bfloat16* __restrict__ OL)
{
    const int row = blockIdx.x;
    const int tid = threadIdx.x, lane = tid & 31;
    __shared__ float red[4];
    __shared__ float sw[4];
    if (tid == 0) {
        const float t = log1pf(expf(ltemp[0])) + 1e-4f;
        float lg[4];
        #pragma unroll
        for (int j = 0; j < 4; ++j)
            lg[j] = PLG[(size_t)row*4 + j] + PLG[((size_t)BL + row)*4 + j]
                  + PLG[((size_t)2*BL + row)*4 + j] + PLG[((size_t)3*BL + row)*4 + j] + b2[j];
        float m = fmaxf(fmaxf(lg[0], lg[1]), fmaxf(lg[2], lg[3]));
        float e[4]; float se = 0.f;
        #pragma unroll
        for (int j = 0; j < 4; ++j) { e[j] = expf((lg[j]-m)/t); se += e[j]; }
        #pragma unroll
        for (int j = 0; j < 4; ++j) e[j] /= se;
        const float fl = 0.05f * e[3];
        e[0] = fmaxf(e[0], fl);
        e[1] = fmaxf(e[1], fl);
        const float s2 = e[0]+e[1]+e[2]+e[3];
        #pragma unroll
        for (int j = 0; j < 4; ++j) sw[j] = e[j]/s2;
    }
    if (tid < 4) red[tid] = 0.f;
    __syncthreads();
    const float w0 = sw[0], w1 = sw[1], w2 = sw[2], w3 = sw[3];
    float ov[4];
    #pragma unroll
    for (int j = 0; j < 4; ++j) {
        const size_t g = (size_t)row*HD + tid + 256*j;
        ov[j] = w0*Sh[g] + w1*Lg[g] + w2*Dl[g] + w3*V[g];
        float v = ov[j]*ov[j];
        #pragma unroll
        for (int o = 16; o; o >>= 1) v += __shfl_xor_sync(0xffffffff, v, o);
        if (lane == 0) atomicAdd(&red[j], v);
    }
    __syncthreads();
    #pragma unroll
    for (int j = 0; j < 4; ++j) {
        const float sc = rsqrtf(red[j]*(1.f/256.f) + 1e-5f) * onw[tid];
        __nv_bfloat16 hh, ll;
        split1(ov[j]*sc, hh, ll);
        OH[(size_t)row*HD + tid + 256*j] = hh;
        OL[(size_t)row*HD + tid + 256*j] = ll;
    }
}

// ---------------- launch ----------------
extern "C" void kernel_launch(void* const* d_in, const int* in_sizes, int n_in,
                              void* d_out, int out_size)
{
    const float* hs  = (const float*)d_in[0];
    const float* qw  = (const float*)d_in[1];
    const float* kw  = (const float*)d_in[2];
    const float* vw  = (const float*)d_in[3];
    const float* bw  = (const float*)d_in[4];
    const float* qcw = (const float*)d_in[5];
    const float* kcw = (const float*)d_in[6];
    const float* vcw = (const float*)d_in[7];
    const float* fsw = (const float*)d_in[8];
    const float* flw = (const float*)d_in[9];
    const float* w1  = (const float*)d_in[10];
    const float* b1  = (const float*)d_in[11];
    const float* w2  = (const float*)d_in[12];
    const float* b2  = (const float*)d_in[13];
    const float* lt  = (const float*)d_in[14];
    const float* onw = (const float*)d_in[15];
    const float* ow  = (const float*)d_in[16];
    float* out = (float*)d_out;

    float *xqkv,*q,*k,*v,*u,*delta,*shrt,*lng,*plg,*beta;
    __nv_bfloat16 *hsH,*hsL,*ginH,*ginL,*ocH,*ocL,*wtH,*wtL;
    __nv_bfloat16 *qh,*ql,*wh,*wlp,*kh,*kl,*ah,*al;
    cudaGetSymbolAddress((void**)&xqkv, g_xqkv);
    cudaGetSymbolAddress((void**)&q,    g_q);
    cudaGetSymbolAddress((void**)&k,    g_k);
    cudaGetSymbolAddress((void**)&v,    g_v);
    cudaGetSymbolAddress((void**)&u,    g_u);
    cudaGetSymbolAddress((void**)&delta,g_delta);
    cudaGetSymbolAddress((void**)&shrt, g_short);
    cudaGetSymbolAddress((void**)&lng,  g_long);
    cudaGetSymbolAddress((void**)&plg,  g_plg);
    cudaGetSymbolAddress((void**)&beta, g_beta);
    cudaGetSymbolAddress((void**)&hsH,  g_hsH);
    cudaGetSymbolAddress((void**)&hsL,  g_hsL);
    cudaGetSymbolAddress((void**)&ginH, g_ginH);
    cudaGetSymbolAddress((void**)&ginL, g_ginL);
    cudaGetSymbolAddress((void**)&ocH,  g_ocH);
    cudaGetSymbolAddress((void**)&ocL,  g_ocL);
    cudaGetSymbolAddress((void**)&wtH,  g_wtH);
    cudaGetSymbolAddress((void**)&wtL,  g_wtL);
    cudaGetSymbolAddress((void**)&qh,   g_qh);
    cudaGetSymbolAddress((void**)&ql,   g_ql);
    cudaGetSymbolAddress((void**)&wh,   g_wh);
    cudaGetSymbolAddress((void**)&wlp,  g_wl);
    cudaGetSymbolAddress((void**)&kh,   g_kh);
    cudaGetSymbolAddress((void**)&kl,   g_kl);
    cudaGetSymbolAddress((void**)&ah,   g_ah);
    cudaGetSymbolAddress((void**)&al,   g_al);

    cudaFuncSetAttribute(precompute_kernel, cudaFuncAttributeMaxDynamicSharedMemorySize, PRE_SMEM);
    cudaFuncSetAttribute(scan_mma, cudaFuncAttributeMaxDynamicSharedMemorySize, SC_SMEM);
    cudaFuncSetAttribute(hgemm_nt<0>, cudaFuncAttributeMaxDynamicSharedMemorySize, G2_SMEM);
    cudaFuncSetAttribute(hgemm_nt<2>, cudaFuncAttributeMaxDynamicSharedMemorySize, G2_SMEM);
    cudaFuncSetAttribute(conv_silu_norm,  cudaFuncAttributeMaxDynamicSharedMemorySize, CV_SMEM);

    {
        int n4 = (BL*Dd) >> 2;
        split_kernel<<<(n4 + 255)/256, 256>>>((const float4*)hs, (uint2*)hsH, (uint2*)hsL, n4);
    }
    wsplit_kernel<<<(W4_O + 255)/256, 256>>>((const float4*)qw, (const float4*)kw,
                                             (const float4*)vw, (const float4*)w1,
                                             (const float4*)ow, (uint2*)wtH, (uint2*)wtL);

    hgemm_nt<0><<<dim3(3072/256, BL/128), 512, G2_SMEM>>>(
        hsH, hsL, wtH+WOFF_Q, wtL+WOFF_Q, xqkv, BL, 3072, Dd, nullptr, nullptr, nullptr);
    beta_kernel<<<BL, 128>>>(hs, bw, beta);
    conv_silu_norm<<<BL/8, 256, CV_SMEM>>>(xqkv, qcw, kcw, vcw, q, k, v);
    precompute_kernel<<<8*NCc, 256, PRE_SMEM>>>(q, k, v, beta, u,
                                                qh, ql, wh, wlp, kh, kl, ah, al);
    scan_mma<<<128, 128, SC_SMEM>>>(qh, ql, wh, wlp, kh, kl, ah, al, u, delta);
    fir_gatein_kernel<<<Bb*(Ll/16), 256>>>((const unsigned*)hsH, (const unsigned*)hsL,
                                           v, fsw, flw, delta, shrt, lng, ginH, ginL);
    hgemm_nt<2><<<dim3(GHID/256, BL/128), 512, G2_SMEM>>>(
        ginH, ginL, wtH+WOFF_W1, wtL+WOFF_W1, nullptr, BL, GHID, GIN, b1, w2, plg);
    combine_kernel<<<BL, 256>>>(shrt, lng, delta, v, plg, b2, lt, onw, ocH, ocL);
    hgemm_nt<0><<<dim3(Dd/256, BL/128), 512, G2_SMEM>>>(
        ocH, ocL, wtH+WOFF_O, wtL+WOFF_O, out, BL, Dd, HD, nullptr, nullptr, nullptr);
}

// round 15
// speedup vs baseline: 1.0183x; 1.0183x over previous
#include <cuda_runtime.h>
#include <cuda_bf16.h>
#include <math.h>

#define Bb   2
#define Ll   4096
#define Dd   1024
#define Hh   4
#define CSs  32
#define NCc  128
#define BL   (Bb*Ll)
#define HD   1024
#define GIN  1792
#define GHID 1024
#define CH8  (8*NCc*8192)

// ---------------- scratch ----------------
__device__ float g_xqkv[BL*3072];
__device__ float g_q [BL*HD];
__device__ float g_k [BL*HD];
__device__ float g_v [BL*HD];
__device__ float g_u [CH8];
__device__ float g_delta[BL*HD];
__device__ float g_short[BL*HD];
__device__ float g_long [BL*HD];
__device__ float g_plg[4*BL*4];
__device__ float g_beta[BL*Hh];

__device__ __align__(16) __nv_bfloat16 g_hsH[BL*Dd];
__device__ __align__(16) __nv_bfloat16 g_hsL[BL*Dd];
__device__ __align__(16) __nv_bfloat16 g_ginH[BL*GIN];
__device__ __align__(16) __nv_bfloat16 g_ginL[BL*GIN];
__device__ __align__(16) __nv_bfloat16 g_ocH[BL*HD];
__device__ __align__(16) __nv_bfloat16 g_ocL[BL*HD];
#define WOFF_Q  0
#define WOFF_K  (1024*1024)
#define WOFF_V  (2*1024*1024)
#define WOFF_W1 (3*1024*1024)
#define WOFF_O  (3*1024*1024 + 1792*1024)
#define WTOT    (WOFF_O + 1024*1024)
__device__ __align__(16) __nv_bfloat16 g_wtH[WTOT];
__device__ __align__(16) __nv_bfloat16 g_wtL[WTOT];

// scan operand planes
__device__ __align__(16) __nv_bfloat16 g_qh[CH8], g_ql[CH8], g_wh[CH8], g_wl[CH8], g_kh[CH8], g_kl[CH8];
__device__ __align__(16) __nv_bfloat16 g_ah[8*NCc*1024], g_al[8*NCc*1024];

// ---------------- helpers ----------------
__device__ __forceinline__ float siluf(float x){ return x / (1.f + expf(-x)); }
__device__ __forceinline__ float geluf(float x){ return 0.5f * x * (1.f + erff(x * 0.70710678118654752f)); }
__device__ __forceinline__ void ldsm4(unsigned* r, unsigned addr){
    asm volatile("ldmatrix.sync.aligned.m8n8.x4.shared.b16 {%0,%1,%2,%3}, [%4];"
        : "=r"(r[0]),"=r"(r[1]),"=r"(r[2]),"=r"(r[3]) : "r"(addr));
}
__device__ __forceinline__ void ldsm4t(unsigned* r, unsigned addr){
    asm volatile("ldmatrix.sync.aligned.m8n8.x4.trans.shared.b16 {%0,%1,%2,%3}, [%4];"
        : "=r"(r[0]),"=r"(r[1]),"=r"(r[2]),"=r"(r[3]) : "r"(addr));
}
__device__ __forceinline__ void ldsm2(unsigned* r, unsigned addr){
    asm volatile("ldmatrix.sync.aligned.m8n8.x2.shared.b16 {%0,%1}, [%2];"
        : "=r"(r[0]),"=r"(r[1]) : "r"(addr));
}
__device__ __forceinline__ void mma16816(float* c, const unsigned* a, const unsigned* b){
    asm volatile("mma.sync.aligned.m16n8k16.row.col.f32.bf16.bf16.f32 "
        "{%0,%1,%2,%3}, {%4,%5,%6,%7}, {%8,%9}, {%0,%1,%2,%3};"
        : "+f"(c[0]),"+f"(c[1]),"+f"(c[2]),"+f"(c[3])
        : "r"(a[0]),"r"(a[1]),"r"(a[2]),"r"(a[3]), "r"(b[0]),"r"(b[1]));
}
__device__ __forceinline__ void cpa16(unsigned d, const void* s){
    asm volatile("cp.async.cg.shared.global [%0],[%1],16;\n" :: "r"(d), "l"(s));
}
#define CP_COMMIT() asm volatile("cp.async.commit_group;\n")
#define CP_WAIT0()  asm volatile("cp.async.wait_group 0;\n")
__device__ __forceinline__ unsigned pack2(float a, float b){
    __nv_bfloat162 t; t.x=__float2bfloat16(a); t.y=__float2bfloat16(b);
    return *(unsigned*)&t;
}
__device__ __forceinline__ float res1(float v){ return v - __bfloat162float(__float2bfloat16(v)); }
__device__ __forceinline__ void split1(float v, __nv_bfloat16& h, __nv_bfloat16& l){
    h = __float2bfloat16(v); l = __float2bfloat16(v - __bfloat162float(h));
}

// ---------------- fused hs split + beta (one block per row) ----------------
__global__ void __launch_bounds__(256) split_hs_beta(
    const float4* __restrict__ x, uint2* __restrict__ hi, uint2* __restrict__ lo,
    const float* __restrict__ bw, float* __restrict__ beta)
{
    const int row = blockIdx.x;
    const int tid = threadIdx.x;
    const int warp = tid >> 5, lane = tid & 31;
    const int i = row*256 + tid;
    float4 v = x[i];
    uint2 ho, loo;
    ho.x = pack2(v.x, v.y);  ho.y = pack2(v.z, v.w);
    loo.x = pack2(res1(v.x), res1(v.y)); loo.y = pack2(res1(v.z), res1(v.w));
    hi[i] = ho; lo[i] = loo;

    __shared__ float red[8][4];
    const int c4 = tid*4;
    float s[4];
    #pragma unroll
    for (int j = 0; j < 4; ++j) {
        const float4 w = *(const float4*)(bw + j*Dd + c4);
        s[j] = v.x*w.x + v.y*w.y + v.z*w.z + v.w*w.w;
    }
    #pragma unroll
    for (int o = 16; o; o >>= 1) {
        #pragma unroll
        for (int j = 0; j < 4; ++j) s[j] += __shfl_xor_sync(0xffffffffu, s[j], o);
    }
    if (lane < 4) red[warp][lane] = s[lane];
    __syncthreads();
    if (tid < 4) {
        float t = 0.f;
        #pragma unroll
        for (int w8 = 0; w8 < 8; ++w8) t += red[w8][tid];
        beta[row*4 + tid] = 1.f / (1.f + expf(-t));
    }
}

// ---------------- merged weight split ----------------
#define W4_Q  262144
#define W4_K  524288
#define W4_V  786432
#define W4_W1 1245184
#define W4_O  1507328
__global__ void wsplit_kernel(const float4* __restrict__ qw, const float4* __restrict__ kw,
                              const float4* __restrict__ vw, const float4* __restrict__ w1,
                              const float4* __restrict__ ow,
                              uint2* __restrict__ hi, uint2* __restrict__ lo)
{
    int i = blockIdx.x*blockDim.x + threadIdx.x;
    if (i >= W4_O) return;
    const float4* src; int local;
    if      (i < W4_Q)  { src = qw; local = i; }
    else if (i < W4_K)  { src = kw; local = i - W4_Q; }
    else if (i < W4_V)  { src = vw; local = i - W4_K; }
    else if (i < W4_W1) { src = w1; local = i - W4_V; }
    else                { src = ow; local = i - W4_W1; }
    float4 v = src[local];
    uint2 ho, loo;
    ho.x = pack2(v.x, v.y);  ho.y = pack2(v.z, v.w);
    loo.x = pack2(res1(v.x), res1(v.y)); loo.y = pack2(res1(v.z), res1(v.w));
    hi[i] = ho; lo[i] = loo;
}

// ---------------- bf16x3 split GEMM, 128x256 tile, 512 threads ----------
#define G2_STG   18432
#define G2_SMEM  (2*G2_STG*2)
template<int MODE>
__global__ void __launch_bounds__(512) hgemm_nt(const __nv_bfloat16* __restrict__ Ah,
                                                const __nv_bfloat16* __restrict__ Al,
                                                const __nv_bfloat16* __restrict__ Bh,
                                                const __nv_bfloat16* __restrict__ Bl,
                                                float* __restrict__ C,
                                                int M, int N, int K,
                                                const float* __restrict__ bias,
                                                const float* __restrict__ W2,
                                                float* __restrict__ PLG)
{
    extern __shared__ __align__(16) __nv_bfloat16 sm[];
    const int tid = threadIdx.x;
    const int bm = blockIdx.y*128, bn = blockIdx.x*256;
    const int warp = tid>>5, lane = tid&31;
    const int wm = warp>>3, wn = warp&7;
    float acc[4][4][4];
    #pragma unroll
    for (int i=0;i<4;i++) for(int j=0;j<4;j++) for(int r=0;r<4;r++) acc[i][j][r]=0.f;

    const bool doA = tid < 256;
    const size_t aoff = (size_t)(bm + ((tid & 255)>>1))*K + (tid&1)*8;
    const size_t boff = (size_t)(bn + (tid>>1))*K + (tid&1)*8;
    const int stoA = ((tid & 255)>>1)*24 + (tid&1)*8;
    const int stoB = 6144 + (tid>>1)*24 + (tid&1)*8;

    unsigned base = (unsigned)__cvta_generic_to_shared(sm);
    const int arow = wm*64 + (lane&15);
    const int acol = (lane>>4)*8;
    const int brow = wn*32 + ((lane>>4)&1)*8 + (lane&7);
    const int bcol = ((lane>>3)&1)*8;
    const int nk = K >> 4;

    {
        uint4 rAh, rAl;
        if (doA) { rAh = *(const uint4*)(Ah + aoff); rAl = *(const uint4*)(Al + aoff); }
        uint4 rBh = *(const uint4*)(Bh + boff);
        uint4 rBl = *(const uint4*)(Bl + boff);
        if (doA) {
            *(uint4*)(sm + stoA) = rAh;
            *(uint4*)(sm + 3072 + stoA) = rAl;
        }
        *(uint4*)(sm + stoB) = rBh;
        *(uint4*)(sm + 6144 + stoB) = rBl;
    }
    __syncthreads();

    for (int kt = 0; kt < nk; ++kt) {
        const int cur = kt & 1;
        const unsigned sb = base + (unsigned)cur*(G2_STG*2);
        uint4 nAh, nAl, nBh, nBl;
        const bool more = (kt + 1 < nk);
        if (more) {
            const size_t kb = boff + (size_t)(kt+1)*16;
            nBh = *(const uint4*)(Bh + kb);
            nBl = *(const uint4*)(Bl + kb);
            if (doA) {
                const size_t ka = aoff + (size_t)(kt+1)*16;
                nAh = *(const uint4*)(Ah + ka);
                nAl = *(const uint4*)(Al + ka);
            }
        }
        unsigned bh[4][2], bl[4][2];
        #pragma unroll
        for (int ng = 0; ng < 2; ++ng) {
            unsigned r4[4];
            ldsm4(r4, sb + 2u*(6144 + (brow + ng*16)*24 + bcol));
            bh[2*ng][0]=r4[0]; bh[2*ng][1]=r4[1]; bh[2*ng+1][0]=r4[2]; bh[2*ng+1][1]=r4[3];
            ldsm4(r4, sb + 2u*(12288 + (brow + ng*16)*24 + bcol));
            bl[2*ng][0]=r4[0]; bl[2*ng][1]=r4[1]; bl[2*ng+1][0]=r4[2]; bl[2*ng+1][1]=r4[3];
        }
        #pragma unroll
        for (int mt = 0; mt < 4; ++mt) {
            unsigned ah[4], al[4];
            ldsm4(ah, sb + 2u*((arow + mt*16)*24 + acol));
            ldsm4(al, sb + 2u*(3072 + (arow + mt*16)*24 + acol));
            #pragma unroll
            for (int nt = 0; nt < 4; ++nt) {
                mma16816(acc[mt][nt], ah, bh[nt]);
                mma16816(acc[mt][nt], ah, bl[nt]);
                mma16816(acc[mt][nt], al, bh[nt]);
            }
        }
        if (more) {
            __nv_bfloat16* d = sm + (cur^1)*G2_STG;
            if (doA) {
                *(uint4*)(d + stoA) = nAh;
                *(uint4*)(d + 3072 + stoA) = nAl;
            }
            *(uint4*)(d + stoB) = nBh;
            *(uint4*)(d + 6144 + stoB) = nBl;
            __syncthreads();
        }
    }
    const int g = lane>>2, tig = lane&3;
    if (MODE == 0) {
        #pragma unroll
        for (int mt = 0; mt < 4; ++mt) {
            const int row0 = bm + wm*64 + mt*16 + g;
            #pragma unroll
            for (int nt = 0; nt < 4; ++nt) {
                const int col = bn + wn*32 + nt*8 + tig*2;
                *(float2*)(C + (size_t)row0*N + col)     = make_float2(acc[mt][nt][0], acc[mt][nt][1]);
                *(float2*)(C + (size_t)(row0+8)*N + col) = make_float2(acc[mt][nt][2], acc[mt][nt][3]);
            }
        }
    } else {
        __syncthreads();
        float* slog = (float*)sm;
        #pragma unroll
        for (int mt = 0; mt < 4; ++mt) {
            #pragma unroll
            for (int half = 0; half < 2; ++half) {
                float pj[4] = {0.f, 0.f, 0.f, 0.f};
                const int rowL = wm*64 + mt*16 + g + half*8;
                #pragma unroll
                for (int nt = 0; nt < 4; ++nt) {
                    #pragma unroll
                    for (int rr = 0; rr < 2; ++rr) {
                        const int col = bn + wn*32 + nt*8 + tig*2 + rr;
                        const float v = geluf(acc[mt][nt][half*2+rr] + bias[col]);
                        #pragma unroll
                        for (int j = 0; j < 4; ++j)
                            pj[j] += v * W2[j*GHID + col];
                    }
                }
                #pragma unroll
                for (int j = 0; j < 4; ++j) {
                    float s = pj[j];
                    s += __shfl_xor_sync(0xffffffffu, s, 1);
                    s += __shfl_xor_sync(0xffffffffu, s, 2);
                    if (tig == 0) slog[wn*512 + rowL*4 + j] = s;
                }
            }
        }
        __syncthreads();
        if (tid < 512) {
            const int row = tid >> 2;
            float s = 0.f;
            #pragma unroll
            for (int w8 = 0; w8 < 8; ++w8) s += slog[w8*512 + tid];
            PLG[((size_t)blockIdx.x*BL + bm + row)*4 + (tid & 3)] = s;
        }
    }
}

// ---------------- conv + silu + l2norm, 8 rows/block ----------------
#define CV_SMEM ((16384 + 64)*4)
__global__ void __launch_bounds__(256) conv_silu_norm(const float* __restrict__ XQKV,
                               const float* __restrict__ WQ, const float* __restrict__ WK,
                               const float* __restrict__ WV,
                               float* __restrict__ Qo, float* __restrict__ Ko,
                               float* __restrict__ Vo)
{
    extern __shared__ float cs[];
    float* sq = cs;
    float* sk = cs + 8192;
    float* red = cs + 16384;
    const int blk = blockIdx.x;
    const int b = blk / (Ll/8);
    const int l0 = (blk % (Ll/8)) * 8;
    const int tid = threadIdx.x;
    const int warp = tid>>5, lane = tid&31;
    if (tid < 64) red[tid] = 0.f;
    __syncthreads();

    #pragma unroll
    for (int j = 0; j < 4; ++j) {
        const int c = tid + 256*j;
        float win[11];
        #pragma unroll
        for (int t = 0; t < 11; ++t) {
            const int l = l0 - 3 + t;
            win[t] = (l >= 0) ? XQKV[((size_t)(b*Ll + l))*3072 + c] : 0.f;
        }
        {
            const float w0 = WQ[c*4+0], w1 = WQ[c*4+1], w2 = WQ[c*4+2], w3 = WQ[c*4+3];
            #pragma unroll
            for (int r = 0; r < 8; ++r)
                sq[r*1024 + c] = siluf(win[r]*w0 + win[r+1]*w1 + win[r+2]*w2 + win[r+3]*w3);
        }
        #pragma unroll
        for (int t = 0; t < 11; ++t) {
            const int l = l0 - 3 + t;
            win[t] = (l >= 0) ? XQKV[((size_t)(b*Ll + l))*3072 + 1024 + c] : 0.f;
        }
        {
            const float w0 = WK[c*4+0], w1 = WK[c*4+1], w2 = WK[c*4+2], w3 = WK[c*4+3];
            #pragma unroll
            for (int r = 0; r < 8; ++r)
                sk[r*1024 + c] = siluf(win[r]*w0 + win[r+1]*w1 + win[r+2]*w2 + win[r+3]*w3);
        }
        #pragma unroll
        for (int t = 0; t < 11; ++t) {
            const int l = l0 - 3 + t;
            win[t] = (l >= 0) ? XQKV[((size_t)(b*Ll + l))*3072 + 2048 + c] : 0.f;
        }
        {
            const float w0 = WV[c*4+0], w1 = WV[c*4+1], w2 = WV[c*4+2], w3 = WV[c*4+3];
            #pragma unroll
            for (int r = 0; r < 8; ++r)
                Vo[((size_t)(b*Ll + l0 + r))*HD + c] =
                    siluf(win[r]*w0 + win[r+1]*w1 + win[r+2]*w2 + win[r+3]*w3);
        }
    }
    __syncthreads();

    #pragma unroll
    for (int gi = 0; gi < 4; ++gi) {
        const int group = warp*4 + gi;
        const int r = group >> 2, h = group & 3;
        float sQ = 0.f, sK = 0.f;
        #pragma unroll
        for (int i = 0; i < 8; ++i) {
            const float vq = sq[r*1024 + h*256 + lane + 32*i];
            const float vk = sk[r*1024 + h*256 + lane + 32*i];
            sQ += vq*vq; sK += vk*vk;
        }
        #pragma unroll
        for (int o = 16; o; o >>= 1) {
            sQ += __shfl_xor_sync(0xffffffff, sQ, o);
            sK += __shfl_xor_sync(0xffffffff, sK, o);
        }
        if (lane == 0) { red[group] = rsqrtf(sQ + 1e-12f); red[32+group] = rsqrtf(sK + 1e-12f); }
    }
    __syncthreads();

    #pragma unroll
    for (int j = 0; j < 4; ++j) {
        const int c = tid + 256*j;
        #pragma unroll
        for (int r = 0; r < 8; ++r) {
            const size_t go = ((size_t)(b*Ll + l0 + r))*HD + c;
            Qo[go] = sq[r*1024 + c] * red[r*4 + j];
            Ko[go] = sk[r*1024 + c] * red[32 + r*4 + j];
        }
    }
}

// ---------------- precompute (tensor-core, beta folded into Tinv; 2 CTAs/SM) ---------
#define OQH 0
#define OQL 16896
#define OKH 33792
#define OKL 50688
#define OVH 67584
#define OVL 84480
#define OTH 101376
#define OTL 103936
#define OAM 106496
#define OTI 110720
#define OSB 114944
#define PRE_SMEM 115072

__global__ void __launch_bounds__(256) precompute_kernel(
    const float* __restrict__ Qn, const float* __restrict__ Kn,
    const float* __restrict__ V,  const float* __restrict__ beta,
    float* __restrict__ U,
    __nv_bfloat16* __restrict__ QH, __nv_bfloat16* __restrict__ QL,
    __nv_bfloat16* __restrict__ WH, __nv_bfloat16* __restrict__ WL,
    __nv_bfloat16* __restrict__ KH, __nv_bfloat16* __restrict__ KL,
    __nv_bfloat16* __restrict__ AH, __nv_bfloat16* __restrict__ AL)
{
    extern __shared__ char smraw[];
    const unsigned smb = (unsigned)__cvta_generic_to_shared(smraw);
    float* Amp = (float*)(smraw + OAM);
    float* Tip = (float*)(smraw + OTI);
    float* sbp = (float*)(smraw + OSB);
    const int idx = blockIdx.x;
    const int bh = idx >> 7, ci = idx & 127;
    const int b = bh >> 2, h = bh & 3;
    const int tid = threadIdx.x, warp = tid>>5, lane = tid&31;
    const int g = lane>>2, qp = (lane&3)*2;
    const size_t cb8 = (size_t)idx*8192;
    const size_t cb1 = (size_t)idx*1024;

    if (tid < 32) sbp[tid] = beta[(size_t)(b*Ll + ci*CSs + tid)*4 + h];
    __syncthreads();

    for (int e = tid; e < 8192; e += 256) {
        const int i = e >> 8, d = e & 255;
        const size_t gg = ((size_t)(b*Ll + ci*CSs + i))*HD + h*256 + d;
        const float qv = Qn[gg], kv = Kn[gg], vv = V[gg];
        __nv_bfloat16 hh, ll;
        split1(qv, hh, ll);
        *(__nv_bfloat16*)(smraw + OQH + (i*264+d)*2) = hh;
        *(__nv_bfloat16*)(smraw + OQL + (i*264+d)*2) = ll;
        QH[cb8+e] = hh; QL[cb8+e] = ll;
        split1(kv, hh, ll);
        *(__nv_bfloat16*)(smraw + OKH + (i*264+d)*2) = hh;
        *(__nv_bfloat16*)(smraw + OKL + (i*264+d)*2) = ll;
        split1(vv, hh, ll);
        *(__nv_bfloat16*)(smraw + OVH + (i*264+d)*2) = hh;
        *(__nv_bfloat16*)(smraw + OVL + (i*264+d)*2) = ll;
    }
    __syncthreads();

    {
        const int mt = warp>>2, ntw = warp&3;
        float qk[4] = {0,0,0,0}, kk[4] = {0,0,0,0};
        const unsigned arow_off = (mt*16 + (lane&15))*528 + ((lane>>4)*8)*2;
        const unsigned brow_off = (ntw*8 + (lane&7))*528 + (((lane>>3)&1)*8)*2;
        #pragma unroll
        for (int kt = 0; kt < 16; ++kt) {
            const unsigned kb2 = kt*32;
            unsigned aq[4], aql[4], ak4[4], akl[4], b2h[2], b2l[2];
            ldsm4(aq,  smb + OQH + arow_off + kb2);
            ldsm4(aql, smb + OQL + arow_off + kb2);
            ldsm4(ak4, smb + OKH + arow_off + kb2);
            ldsm4(akl, smb + OKL + arow_off + kb2);
            ldsm2(b2h, smb + OKH + brow_off + kb2);
            ldsm2(b2l, smb + OKL + brow_off + kb2);
            mma16816(qk, aq, b2h);  mma16816(qk, aql, b2h); mma16816(qk, aq, b2l);
            mma16816(kk, ak4, b2h); mma16816(kk, akl, b2h); mma16816(kk, ak4, b2l);
        }
        const int i0 = mt*16 + g, j0 = ntw*8 + qp;
        #pragma unroll
        for (int r = 0; r < 4; ++r) {
            const int i = i0 + (r>>1)*8, j = j0 + (r&1);
            Amp[i*33+j] = (i > j) ? sbp[i]*kk[r] : 0.f;
            const float av = (i >= j) ? qk[r] : 0.f;
            __nv_bfloat16 hh, ll;
            split1(av, hh, ll);
            AH[cb1 + i*32 + j] = hh; AL[cb1 + i*32 + j] = ll;
        }
    }
    for (int e = tid; e < 8192; e += 256) {
        const int d = e >> 5, t = e & 31;
        unsigned short hv = *(unsigned short*)(smraw + OKH + (t*264+d)*2) ^ 0x8000u;
        unsigned short lv = *(unsigned short*)(smraw + OKL + (t*264+d)*2) ^ 0x8000u;
        KH[cb8+e] = *(__nv_bfloat16*)&hv;
        KL[cb8+e] = *(__nv_bfloat16*)&lv;
    }
    __syncthreads();

    if (tid < 32) {
        const int j = tid;
        Tip[j] = (j == 0) ? 1.f : 0.f;
        for (int i2 = 1; i2 < 32; ++i2) {
            __syncwarp();
            float s = 0.f;
            for (int m = 0; m < i2; ++m) s += Amp[i2*33+m]*Tip[m*33+j];
            Tip[i2*33+j] = ((i2 == j) ? 1.f : 0.f) - s;
        }
    }
    __syncthreads();
    for (int e = tid; e < 1024; e += 256) {
        const int i = e >> 5, j = e & 31;
        __nv_bfloat16 hh, ll;
        split1(Tip[i*33+j] * sbp[j], hh, ll);
        *(__nv_bfloat16*)(smraw + OTH + (i*40+j)*2) = hh;
        *(__nv_bfloat16*)(smraw + OTL + (i*40+j)*2) = ll;
    }
    __syncthreads();

    {
        const int mt = warp>>2;
        unsigned TiH[2][4], TiL[2][4];
        #pragma unroll
        for (int kt = 0; kt < 2; ++kt) {
            const unsigned ao = (mt*16 + (lane&15))*80 + (kt*16 + (lane>>4)*8)*2;
            ldsm4(TiH[kt], smb + OTH + ao);
            ldsm4(TiL[kt], smb + OTL + ao);
        }
        const int i0 = mt*16 + g;
        #pragma unroll
        for (int ng = 0; ng < 4; ++ng) {
            const int n0 = (warp&3)*64 + ng*16;
            float aU[2][4], aW[2][4];
            #pragma unroll
            for (int t2 = 0; t2 < 2; ++t2)
                #pragma unroll
                for (int r = 0; r < 4; ++r) { aU[t2][r]=0.f; aW[t2][r]=0.f; }
            #pragma unroll
            for (int kt = 0; kt < 2; ++kt) {
                const unsigned brow = kt*16 + (lane&7) + ((lane>>3)&1)*8;
                const unsigned bcol = n0 + ((lane>>4)&1)*8;
                const unsigned bo = brow*528 + bcol*2;
                unsigned bvh[4], bvl[4], bbh[4], bbl[4];
                ldsm4t(bvh, smb + OVH + bo);
                ldsm4t(bvl, smb + OVL + bo);
                ldsm4t(bbh, smb + OKH + bo);
                ldsm4t(bbl, smb + OKL + bo);
                #pragma unroll
                for (int nt = 0; nt < 2; ++nt) {
                    mma16816(aU[nt], TiH[kt], bvh+2*nt);
                    mma16816(aU[nt], TiL[kt], bvh+2*nt);
                    mma16816(aU[nt], TiH[kt], bvl+2*nt);
                    mma16816(aW[nt], TiH[kt], bbh+2*nt);
                    mma16816(aW[nt], TiL[kt], bbh+2*nt);
                    mma16816(aW[nt], TiH[kt], bbl+2*nt);
                }
            }
            #pragma unroll
            for (int nt = 0; nt < 2; ++nt)
                #pragma unroll
                for (int r = 0; r < 4; ++r) {
                    const int i = i0 + (r>>1)*8;
                    const int d = n0 + nt*8 + qp + (r&1);
                    U[cb8 + i*256 + d] = aU[nt][r];
                    __nv_bfloat16 hh, ll;
                    split1(aW[nt][r], hh, ll);
                    WH[cb8 + i*256 + d] = hh;
                    WL[cb8 + i*256 + d] = ll;
                }
        }
    }
}

// ---------------- tensor-core delta scan (R13 schedule) ----------------
#define STGSZ  72704
#define OFF_KT 145408
#define OFF_UB 210944
#define SC_SMEM 227840

__global__ void __launch_bounds__(128) scan_mma(
    const __nv_bfloat16* __restrict__ QHp, const __nv_bfloat16* __restrict__ QLp,
    const __nv_bfloat16* __restrict__ WHp, const __nv_bfloat16* __restrict__ WLp,
    const __nv_bfloat16* __restrict__ KHp, const __nv_bfloat16* __restrict__ KLp,
    const __nv_bfloat16* __restrict__ AHp, const __nv_bfloat16* __restrict__ ALp,
    const float* __restrict__ Ug, float* __restrict__ Out)
{
    extern __shared__ char smraw[];
    const unsigned smb = (unsigned)__cvta_generic_to_shared(smraw);
    float* ub = (float*)(smraw + OFF_UB);
    const int tid = threadIdx.x, warp = tid>>5, lane = tid&31;
    const int bh = blockIdx.x>>4, cb = blockIdx.x&15;
    const int b = bh>>2, h = bh&3;
    const int g = lane>>2, qp = (lane&3)*2;
    const int brow16 = ((lane>>4)&1)*8 + (lane&7);
    const int bcol8 = ((lane>>3)&1)*8;

    float P[8][4];
    #pragma unroll
    for (int i=0;i<8;++i)
        #pragma unroll
        for (int r=0;r<4;++r) P[i][r]=0.f;

    auto issue = [&](int ci, int stg){
        const size_t b8 = (size_t)(bh*NCc + ci)*8192;
        const size_t b1 = (size_t)(bh*NCc + ci)*1024;
        const unsigned sb = smb + stg*STGSZ;
        const __nv_bfloat16* srcs[4] = {QHp+b8, QLp+b8, WHp+b8, WLp+b8};
        #pragma unroll
        for (int pl = 0; pl < 4; ++pl){
            const unsigned dsb = sb + pl*16384;
            for (int e = tid; e < 1024; e += 128){
                int row = e>>5, c = e&31;
                cpa16(dsb + row*512 + ((c^(row&7))<<4), srcs[pl] + row*256 + c*8);
            }
        }
        const unsigned kb2 = smb + OFF_KT + stg*32768;
        for (int e = tid; e < 1024; e += 128){
            int row = e>>2, c = e&3;
            cpa16(kb2 + row*64 + c*16, KHp + b8 + row*32 + c*8);
            cpa16(kb2 + 16384 + row*64 + c*16, KLp + b8 + row*32 + c*8);
        }
        {
            int row = tid>>2, c = tid&3;
            cpa16(sb + 65536 + row*80 + c*16, AHp + b1 + row*32 + c*8);
            cpa16(sb + 68096 + row*80 + c*16, ALp + b1 + row*32 + c*8);
            cpa16(sb + 70656 + row*64 + c*16, Ug + b8 + (size_t)row*256 + cb*16 + c*4);
        }
    };

    issue(0, 0); CP_COMMIT();

    for (int ci = 0; ci < NCc; ++ci) {
        const int stg = ci & 1;
        const unsigned sb = smb + stg*STGSZ;
        const unsigned kb = smb + OFF_KT + stg*32768;
        CP_WAIT0();
        __syncthreads();

        float accW[4][4], accQ[4][4];
        #pragma unroll
        for (int i=0;i<4;++i)
            #pragma unroll
            for (int r=0;r<4;++r){ accW[i][r]=0.f; accQ[i][r]=0.f; }
        #pragma unroll
        for (int kt = 0; kt < 4; ++kt) {
            unsigned Ah[4], Al[4];
            const float* p0 = P[2*kt]; const float* p1 = P[2*kt+1];
            Ah[0]=pack2(p0[0],p0[1]); Ah[1]=pack2(p0[2],p0[3]);
            Ah[2]=pack2(p1[0],p1[1]); Ah[3]=pack2(p1[2],p1[3]);
            Al[0]=pack2(res1(p0[0]),res1(p0[1])); Al[1]=pack2(res1(p0[2]),res1(p0[3]));
            Al[2]=pack2(res1(p1[0]),res1(p1[1])); Al[3]=pack2(res1(p1[2]),res1(p1[3]));
            const int dcol = warp*64 + kt*16 + bcol8;
            unsigned bwh[4][2], bwl[4][2], bqh[4][2], bql[4][2];
            #pragma unroll
            for (int ng = 0; ng < 2; ++ng) {
                const int row = ng*16 + brow16;
                const unsigned off = row*512 + ((((unsigned)(dcol>>3))^(row&7))<<4);
                unsigned r4[4];
                ldsm4(r4, sb + 32768 + off);
                bwh[2*ng][0]=r4[0]; bwh[2*ng][1]=r4[1]; bwh[2*ng+1][0]=r4[2]; bwh[2*ng+1][1]=r4[3];
                ldsm4(r4, sb + 49152 + off);
                bwl[2*ng][0]=r4[0]; bwl[2*ng][1]=r4[1]; bwl[2*ng+1][0]=r4[2]; bwl[2*ng+1][1]=r4[3];
                ldsm4(r4, sb + off);
                bqh[2*ng][0]=r4[0]; bqh[2*ng][1]=r4[1]; bqh[2*ng+1][0]=r4[2]; bqh[2*ng+1][1]=r4[3];
                ldsm4(r4, sb + 16384 + off);
                bql[2*ng][0]=r4[0]; bql[2*ng][1]=r4[1]; bql[2*ng+1][0]=r4[2]; bql[2*ng+1][1]=r4[3];
            }
            #pragma unroll
            for (int nt = 0; nt < 4; ++nt) {
                mma16816(accW[nt], Ah, bwh[nt]);
                mma16816(accW[nt], Al, bwh[nt]);
                mma16816(accW[nt], Ah, bwl[nt]);
                mma16816(accQ[nt], Ah, bqh[nt]);
                mma16816(accQ[nt], Al, bqh[nt]);
                mma16816(accQ[nt], Ah, bql[nt]);
            }
        }
        #pragma unroll
        for (int nt = 0; nt < 4; ++nt)
            #pragma unroll
            for (int r = 0; r < 4; ++r) {
                int c = g + ((r>>1)<<3), t = nt*8 + qp + (r&1);
                ub[(c*4+warp)*66 + t] = accW[nt][r];
                ub[(c*4+warp)*66 + 32 + t] = accQ[nt][r];
            }
        if (ci + 1 < NCc) { issue(ci+1, stg^1); CP_COMMIT(); }
        __syncthreads();

        const float* su = (const float*)(smraw + stg*STGSZ + 70656);
        unsigned UH[2][4], UL[2][4];
        #pragma unroll
        for (int kt = 0; kt < 2; ++kt) {
            float v[8];
            #pragma unroll
            for (int p = 0; p < 8; ++p) {
                const int c = g + (((p>>1)&1)<<3);
                const int t = kt*16 + qp + (p&1) + ((p>>2)<<3);
                const int bi = (c*4)*66 + t;
                v[p] = su[t*16 + c] + ub[bi] + ub[bi+66] + ub[bi+132] + ub[bi+198];
            }
            UH[kt][0]=pack2(v[0],v[1]); UH[kt][1]=pack2(v[2],v[3]);
            UH[kt][2]=pack2(v[4],v[5]); UH[kt][3]=pack2(v[6],v[7]);
            UL[kt][0]=pack2(res1(v[0]),res1(v[1])); UL[kt][1]=pack2(res1(v[2]),res1(v[3]));
            UL[kt][2]=pack2(res1(v[4]),res1(v[5])); UL[kt][3]=pack2(res1(v[6]),res1(v[7]));
        }
        float oc[4];
        const int i0 = warp*8 + qp;
        #pragma unroll
        for (int r = 0; r < 4; ++r) {
            const int c = g + ((r>>1)<<3);
            const int bi = (c*4)*66 + 32 + i0 + (r&1);
            oc[r] = -(ub[bi] + ub[bi+66] + ub[bi+132] + ub[bi+198]);
        }

        #pragma unroll
        for (int kt = 0; kt < 2; ++kt) {
            unsigned bh2[2], bl2[2];
            const unsigned aoff = (warp*8 + (lane&7))*80 + (kt*16 + bcol8)*2;
            ldsm2(bh2, sb + 65536 + aoff);
            ldsm2(bl2, sb + 68096 + aoff);
            mma16816(oc, UH[kt], bh2);
            mma16816(oc, UL[kt], bh2);
            mma16816(oc, UH[kt], bl2);
        }
        {
            const size_t base = ((size_t)(b*Ll + ci*CSs + i0))*HD + h*256 + cb*16;
            Out[base + g]          = oc[0];
            Out[base + HD + g]     = oc[1];
            Out[base + g + 8]      = oc[2];
            Out[base + HD + g + 8] = oc[3];
        }

        #pragma unroll
        for (int kt = 0; kt < 2; ++kt) {
            #pragma unroll
            for (int np = 0; np < 4; ++np) {
                unsigned bh4[4], bl4[4];
                const unsigned off = (warp*64 + np*16 + brow16)*64 + (kt*16 + bcol8)*2;
                ldsm4(bh4, kb + off);
                ldsm4(bl4, kb + 16384 + off);
                mma16816(P[2*np],   UH[kt], bh4);
                mma16816(P[2*np],   UL[kt], bh4);
                mma16816(P[2*np],   UH[kt], bl4);
                mma16816(P[2*np+1], UH[kt], bh4+2);
                mma16816(P[2*np+1], UL[kt], bh4+2);
                mma16816(P[2*np+1], UH[kt], bl4+2);
            }
        }
    }
}

// ---------------- FIR short/long + gate_in, 16 rows/block (R13 version) ----------
__global__ void __launch_bounds__(256) fir_gatein_kernel(
                                  const unsigned* __restrict__ hsHu, const unsigned* __restrict__ hsLu,
                                  const float* __restrict__ V,
                                  const float* __restrict__ ws, const float* __restrict__ wl,
                                  const float* __restrict__ Dl,
                                  float* __restrict__ Sout, float* __restrict__ Lout,
                                  __nv_bfloat16* __restrict__ GinH, __nv_bfloat16* __restrict__ GinL)
{
    const int blk = blockIdx.x;
    const int b = blk / (Ll/16);
    const int l0 = (blk % (Ll/16)) * 16;
    const int tid = threadIdx.x;
    float smean[16], lmean[16], dmean[16];
    #pragma unroll
    for (int r = 0; r < 16; ++r) { smean[r]=0.f; lmean[r]=0.f; dmean[r]=0.f; }
    for (int j = 0; j < 4; ++j) {
        const int ch = tid + 256*j;
        float win[46];
        #pragma unroll
        for (int t = 0; t < 46; ++t) {
            const int l = l0 - 30 + t;
            win[t] = (l >= 0) ? V[((size_t)(b*Ll + l))*HD + ch] : 0.f;
        }
        float wlr[31];
        #pragma unroll
        for (int t = 0; t < 31; ++t) wlr[t] = wl[ch*31 + t];
        const float w0 = ws[ch*3+0], w1 = ws[ch*3+1], w2 = ws[ch*3+2];
        #pragma unroll
        for (int r = 0; r < 16; ++r) {
            float yl = 0.f;
            #pragma unroll
            for (int t = 0; t < 31; ++t) yl += win[r+t]*wlr[t];
            const float ysv = win[r+28]*w0 + win[r+29]*w1 + win[r+30]*w2;
            const size_t row = (size_t)(b*Ll + l0 + r);
            Sout[row*HD + ch] = ysv;
            Lout[row*HD + ch] = yl;
            smean[r] += ysv; lmean[r] += yl;
            dmean[r] += Dl[row*HD + ch];
        }
    }
    for (int r = 0; r < 16; ++r) {
        const size_t row = (size_t)(b*Ll + l0 + r);
        __nv_bfloat16* gH = GinH + row*GIN;
        __nv_bfloat16* gL = GinL + row*GIN;
        #pragma unroll
        for (int j = 0; j < 2; ++j) {
            const int e = tid + 256*j;
            ((unsigned*)gH)[e] = hsHu[row*512 + e];
            ((unsigned*)gL)[e] = hsLu[row*512 + e];
        }
        __nv_bfloat16 hh, ll;
        split1(smean[r]*0.25f, hh, ll);
        gH[1024 + tid] = hh; gL[1024 + tid] = ll;
        split1(lmean[r]*0.25f, hh, ll);
        gH[1280 + tid] = hh; gL[1280 + tid] = ll;
        split1(dmean[r]*0.25f, hh, ll);
        gH[1536 + tid] = hh; gL[1536 + tid] = ll;
    }
}

// ---------------- combine + gate softmax + RMSNorm ----------------
__global__ void combine_kernel(const float* __restrict__ Sh, const float* __restrict__ Lg,
                               const float* __restrict__ Dl, const float* __restrict__ V,
                               const float* __restrict__ PLG, const float* __restrict__ b2,
                               const float* __restrict__ ltemp, const float* __restrict__ onw,
                               __nv_bfloat16* __restrict__ OH, __nv_bfloat16* __restrict__ OL)
{
    const int row = blockIdx.x;
    const int tid = threadIdx.x, lane = tid & 31;
    __shared__ float red[4];
    __shared__ float sw[4];
    if (tid == 0) {
        const float t = log1pf(expf(ltemp[0])) + 1e-4f;
        float lg[4];
        #pragma unroll
        for (int j = 0; j < 4; ++j)
            lg[j] = PLG[(size_t)row*4 + j] + PLG[((size_t)BL + row)*4 + j]
                  + PLG[((size_t)2*BL + row)*4 + j] + PLG[((size_t)3*BL + row)*4 + j] + b2[j];
        float m = fmaxf(fmaxf(lg[0], lg[1]), fmaxf(lg[2], lg[3]));
        float e[4]; float se = 0.f;
        #pragma unroll
        for (int j = 0; j < 4; ++j) { e[j] = expf((lg[j]-m)/t); se += e[j]; }
        #pragma unroll
        for (int j = 0; j < 4; ++j) e[j] /= se;
        const float fl = 0.05f * e[3];
        e[0] = fmaxf(e[0], fl);
        e[1] = fmaxf(e[1], fl);
        const float s2 = e[0]+e[1]+e[2]+e[3];
        #pragma unroll
        for (int j = 0; j < 4; ++j) sw[j] = e[j]/s2;
    }
    if (tid < 4) red[tid] = 0.f;
    __syncthreads();
    const float w0 = sw[0], w1 = sw[1], w2 = sw[2], w3 = sw[3];
    float ov[4];
    #pragma unroll
    for (int j = 0; j < 4; ++j) {
        const size_t g = (size_t)row*HD + tid + 256*j;
        ov[j] = w0*Sh[g] + w1*Lg[g] + w2*Dl[g] + w3*V[g];
        float v = ov[j]*ov[j];
        #pragma unroll
        for (int o = 16; o; o >>= 1) v += __shfl_xor_sync(0xffffffff, v, o);
        if (lane == 0) atomicAdd(&red[j], v);
    }
    __syncthreads();
    #pragma unroll
    for (int j = 0; j < 4; ++j) {
        const float sc = rsqrtf(red[j]*(1.f/256.f) + 1e-5f) * onw[tid];
        __nv_bfloat16 hh, ll;
        split1(ov[j]*sc, hh, ll);
        OH[(size_t)row*HD + tid + 256*j] = hh;
        OL[(size_t)row*HD + tid + 256*j] = ll;
    }
}

// ---------------- launch ----------------
extern "C" void kernel_launch(void* const* d_in, const int* in_sizes, int n_in,
                              void* d_out, int out_size)
{
    const float* hs  = (const float*)d_in[0];
    const float* qw  = (const float*)d_in[1];
    const float* kw  = (const float*)d_in[2];
    const float* vw  = (const float*)d_in[3];
    const float* bw  = (const float*)d_in[4];
    const float* qcw = (const float*)d_in[5];
    const float* kcw = (const float*)d_in[6];
    const float* vcw = (const float*)d_in[7];
    const float* fsw = (const float*)d_in[8];
    const float* flw = (const float*)d_in[9];
    const float* w1  = (const float*)d_in[10];
    const float* b1  = (const float*)d_in[11];
    const float* w2  = (const float*)d_in[12];
    const float* b2  = (const float*)d_in[13];
    const float* lt  = (const float*)d_in[14];
    const float* onw = (const float*)d_in[15];
    const float* ow  = (const float*)d_in[16];
    float* out = (float*)d_out;

    float *xqkv,*q,*k,*v,*u,*delta,*shrt,*lng,*plg,*beta;
    __nv_bfloat16 *hsH,*hsL,*ginH,*ginL,*ocH,*ocL,*wtH,*wtL;
    __nv_bfloat16 *qh,*ql,*wh,*wlp,*kh,*kl,*ah,*al;
    cudaGetSymbolAddress((void**)&xqkv, g_xqkv);
    cudaGetSymbolAddress((void**)&q,    g_q);
    cudaGetSymbolAddress((void**)&k,    g_k);
    cudaGetSymbolAddress((void**)&v,    g_v);
    cudaGetSymbolAddress((void**)&u,    g_u);
    cudaGetSymbolAddress((void**)&delta,g_delta);
    cudaGetSymbolAddress((void**)&shrt, g_short);
    cudaGetSymbolAddress((void**)&lng,  g_long);
    cudaGetSymbolAddress((void**)&plg,  g_plg);
    cudaGetSymbolAddress((void**)&beta, g_beta);
    cudaGetSymbolAddress((void**)&hsH,  g_hsH);
    cudaGetSymbolAddress((void**)&hsL,  g_hsL);
    cudaGetSymbolAddress((void**)&ginH, g_ginH);
    cudaGetSymbolAddress((void**)&ginL, g_ginL);
    cudaGetSymbolAddress((void**)&ocH,  g_ocH);
    cudaGetSymbolAddress((void**)&ocL,  g_ocL);
    cudaGetSymbolAddress((void**)&wtH,  g_wtH);
    cudaGetSymbolAddress((void**)&wtL,  g_wtL);
    cudaGetSymbolAddress((void**)&qh,   g_qh);
    cudaGetSymbolAddress((void**)&ql,   g_ql);
    cudaGetSymbolAddress((void**)&wh,   g_wh);
    cudaGetSymbolAddress((void**)&wlp,  g_wl);
    cudaGetSymbolAddress((void**)&kh,   g_kh);
    cudaGetSymbolAddress((void**)&kl,   g_kl);
    cudaGetSymbolAddress((void**)&ah,   g_ah);
    cudaGetSymbolAddress((void**)&al,   g_al);

    cudaFuncSetAttribute(precompute_kernel, cudaFuncAttributeMaxDynamicSharedMemorySize, PRE_SMEM);
    cudaFuncSetAttribute(scan_mma, cudaFuncAttributeMaxDynamicSharedMemorySize, SC_SMEM);
    cudaFuncSetAttribute(hgemm_nt<0>, cudaFuncAttributeMaxDynamicSharedMemorySize, G2_SMEM);
    cudaFuncSetAttribute(hgemm_nt<2>, cudaFuncAttributeMaxDynamicSharedMemorySize, G2_SMEM);
    cudaFuncSetAttribute(conv_silu_norm,  cudaFuncAttributeMaxDynamicSharedMemorySize, CV_SMEM);

    split_hs_beta<<<BL, 256>>>((const float4*)hs, (uint2*)hsH, (uint2*)hsL, bw, beta);
    wsplit_kernel<<<(W4_O + 255)/256, 256>>>((const float4*)qw, (const float4*)kw,
                                             (const float4*)vw, (const float4*)w1,
                                             (const float4*)ow, (uint2*)wtH, (uint2*)wtL);

    hgemm_nt<0><<<dim3(3072/256, BL/128), 512, G2_SMEM>>>(
        hsH, hsL, wtH+WOFF_Q, wtL+WOFF_Q, xqkv, BL, 3072, Dd, nullptr, nullptr, nullptr);
    conv_silu_norm<<<BL/8, 256, CV_SMEM>>>(xqkv, qcw, kcw, vcw, q, k, v);
    precompute_kernel<<<8*NCc, 256, PRE_SMEM>>>(q, k, v, beta, u,
                                                qh, ql, wh, wlp, kh, kl, ah, al);
    scan_mma<<<128, 128, SC_SMEM>>>(qh, ql, wh, wlp, kh, kl, ah, al, u, delta);
    fir_gatein_kernel<<<Bb*(Ll/16), 256>>>((const unsigned*)hsH, (const unsigned*)hsL,
                                           v, fsw, flw, delta, shrt, lng, ginH, ginL);
    hgemm_nt<2><<<dim3(GHID/256, BL/128), 512, G2_SMEM>>>(
        ginH, ginL, wtH+WOFF_W1, wtL+WOFF_W1, nullptr, BL, GHID, GIN, b1, w2, plg);
    combine_kernel<<<BL, 256>>>(shrt, lng, delta, v, plg, b2, lt, onw, ocH, ocL);
    hgemm_nt<0><<<dim3(Dd/256, BL/128), 512, G2_SMEM>>>(
        ocH, ocL, wtH+WOFF_O, wtL+WOFF_O, out, BL, Dd, HD, nullptr, nullptr, nullptr);
}

// round 16
// speedup vs baseline: 1.0241x; 1.0057x over previous
#include <cuda_runtime.h>
#include <cuda_bf16.h>
#include <math.h>

#define Bb   2
#define Ll   4096
#define Dd   1024
#define Hh   4
#define CSs  32
#define NCc  128
#define BL   (Bb*Ll)
#define HD   1024
#define GIN  1792
#define GHID 1024
#define CH8  (8*NCc*8192)

// ---------------- scratch ----------------
__device__ float g_xqkv[BL*3072];
__device__ float g_q [BL*HD];
__device__ float g_k [BL*HD];
__device__ float g_v [BL*HD];
__device__ float g_u [CH8];
__device__ float g_delta[BL*HD];
__device__ float g_short[BL*HD];
__device__ float g_long [BL*HD];
__device__ float g_plg[4*BL*4];
__device__ float g_beta[BL*Hh];

__device__ __align__(16) __nv_bfloat16 g_hsH[BL*Dd];
__device__ __align__(16) __nv_bfloat16 g_hsL[BL*Dd];
__device__ __align__(16) __nv_bfloat16 g_ginH[BL*GIN];
__device__ __align__(16) __nv_bfloat16 g_ginL[BL*GIN];
__device__ __align__(16) __nv_bfloat16 g_ocH[BL*HD];
__device__ __align__(16) __nv_bfloat16 g_ocL[BL*HD];
#define WOFF_Q  0
#define WOFF_K  (1024*1024)
#define WOFF_V  (2*1024*1024)
#define WOFF_W1 (3*1024*1024)
#define WOFF_O  (3*1024*1024 + 1792*1024)
#define WTOT    (WOFF_O + 1024*1024)
__device__ __align__(16) __nv_bfloat16 g_wtH[WTOT];
__device__ __align__(16) __nv_bfloat16 g_wtL[WTOT];

// scan operand planes
__device__ __align__(16) __nv_bfloat16 g_qh[CH8], g_ql[CH8], g_wh[CH8], g_wl[CH8], g_kh[CH8], g_kl[CH8];
__device__ __align__(16) __nv_bfloat16 g_ah[8*NCc*1024], g_al[8*NCc*1024];

// ---------------- helpers ----------------
__device__ __forceinline__ float siluf(float x){ return x / (1.f + expf(-x)); }
__device__ __forceinline__ float geluf(float x){ return 0.5f * x * (1.f + erff(x * 0.70710678118654752f)); }
__device__ __forceinline__ void ldsm4(unsigned* r, unsigned addr){
    asm volatile("ldmatrix.sync.aligned.m8n8.x4.shared.b16 {%0,%1,%2,%3}, [%4];"
        : "=r"(r[0]),"=r"(r[1]),"=r"(r[2]),"=r"(r[3]) : "r"(addr));
}
__device__ __forceinline__ void ldsm4t(unsigned* r, unsigned addr){
    asm volatile("ldmatrix.sync.aligned.m8n8.x4.trans.shared.b16 {%0,%1,%2,%3}, [%4];"
        : "=r"(r[0]),"=r"(r[1]),"=r"(r[2]),"=r"(r[3]) : "r"(addr));
}
__device__ __forceinline__ void ldsm2(unsigned* r, unsigned addr){
    asm volatile("ldmatrix.sync.aligned.m8n8.x2.shared.b16 {%0,%1}, [%2];"
        : "=r"(r[0]),"=r"(r[1]) : "r"(addr));
}
__device__ __forceinline__ void mma16816(float* c, const unsigned* a, const unsigned* b){
    asm volatile("mma.sync.aligned.m16n8k16.row.col.f32.bf16.bf16.f32 "
        "{%0,%1,%2,%3}, {%4,%5,%6,%7}, {%8,%9}, {%0,%1,%2,%3};"
        : "+f"(c[0]),"+f"(c[1]),"+f"(c[2]),"+f"(c[3])
        : "r"(a[0]),"r"(a[1]),"r"(a[2]),"r"(a[3]), "r"(b[0]),"r"(b[1]));
}
__device__ __forceinline__ void cpa16(unsigned d, const void* s){
    asm volatile("cp.async.cg.shared.global [%0],[%1],16;\n" :: "r"(d), "l"(s));
}
#define CP_COMMIT() asm volatile("cp.async.commit_group;\n")
#define CP_WAIT0()  asm volatile("cp.async.wait_group 0;\n")
__device__ __forceinline__ unsigned pack2(float a, float b){
    __nv_bfloat162 t; t.x=__float2bfloat16(a); t.y=__float2bfloat16(b);
    return *(unsigned*)&t;
}
__device__ __forceinline__ float res1(float v){ return v - __bfloat162float(__float2bfloat16(v)); }
__device__ __forceinline__ void split1(float v, __nv_bfloat16& h, __nv_bfloat16& l){
    h = __float2bfloat16(v); l = __float2bfloat16(v - __bfloat162float(h));
}

// ---------------- fused hs split + beta (one block per row) ----------------
__global__ void __launch_bounds__(256) split_hs_beta(
    const float4* __restrict__ x, uint2* __restrict__ hi, uint2* __restrict__ lo,
    const float* __restrict__ bw, float* __restrict__ beta)
{
    const int row = blockIdx.x;
    const int tid = threadIdx.x;
    const int warp = tid >> 5, lane = tid & 31;
    const int i = row*256 + tid;
    float4 v = x[i];
    uint2 ho, loo;
    ho.x = pack2(v.x, v.y);  ho.y = pack2(v.z, v.w);
    loo.x = pack2(res1(v.x), res1(v.y)); loo.y = pack2(res1(v.z), res1(v.w));
    hi[i] = ho; lo[i] = loo;

    __shared__ float red[8][4];
    const int c4 = tid*4;
    float s[4];
    #pragma unroll
    for (int j = 0; j < 4; ++j) {
        const float4 w = *(const float4*)(bw + j*Dd + c4);
        s[j] = v.x*w.x + v.y*w.y + v.z*w.z + v.w*w.w;
    }
    #pragma unroll
    for (int o = 16; o; o >>= 1) {
        #pragma unroll
        for (int j = 0; j < 4; ++j) s[j] += __shfl_xor_sync(0xffffffffu, s[j], o);
    }
    if (lane < 4) red[warp][lane] = s[lane];
    __syncthreads();
    if (tid < 4) {
        float t = 0.f;
        #pragma unroll
        for (int w8 = 0; w8 < 8; ++w8) t += red[w8][tid];
        beta[row*4 + tid] = 1.f / (1.f + expf(-t));
    }
}

// ---------------- merged weight split ----------------
#define W4_Q  262144
#define W4_K  524288
#define W4_V  786432
#define W4_W1 1245184
#define W4_O  1507328
__global__ void wsplit_kernel(const float4* __restrict__ qw, const float4* __restrict__ kw,
                              const float4* __restrict__ vw, const float4* __restrict__ w1,
                              const float4* __restrict__ ow,
                              uint2* __restrict__ hi, uint2* __restrict__ lo)
{
    int i = blockIdx.x*blockDim.x + threadIdx.x;
    if (i >= W4_O) return;
    const float4* src; int local;
    if      (i < W4_Q)  { src = qw; local = i; }
    else if (i < W4_K)  { src = kw; local = i - W4_Q; }
    else if (i < W4_V)  { src = vw; local = i - W4_K; }
    else if (i < W4_W1) { src = w1; local = i - W4_V; }
    else                { src = ow; local = i - W4_W1; }
    float4 v = src[local];
    uint2 ho, loo;
    ho.x = pack2(v.x, v.y);  ho.y = pack2(v.z, v.w);
    loo.x = pack2(res1(v.x), res1(v.y)); loo.y = pack2(res1(v.z), res1(v.w));
    hi[i] = ho; lo[i] = loo;
}

// ---------------- bf16x3 split GEMM, 128x256 tile, 512 threads ----------
#define G2_STG   18432
#define G2_SMEM  (2*G2_STG*2)
template<int MODE>
__global__ void __launch_bounds__(512) hgemm_nt(const __nv_bfloat16* __restrict__ Ah,
                                                const __nv_bfloat16* __restrict__ Al,
                                                const __nv_bfloat16* __restrict__ Bh,
                                                const __nv_bfloat16* __restrict__ Bl,
                                                float* __restrict__ C,
                                                int M, int N, int K,
                                                const float* __restrict__ bias,
                                                const float* __restrict__ W2,
                                                float* __restrict__ PLG)
{
    extern __shared__ __align__(16) __nv_bfloat16 sm[];
    const int tid = threadIdx.x;
    const int bm = blockIdx.y*128, bn = blockIdx.x*256;
    const int warp = tid>>5, lane = tid&31;
    const int wm = warp>>3, wn = warp&7;
    float acc[4][4][4];
    #pragma unroll
    for (int i=0;i<4;i++) for(int j=0;j<4;j++) for(int r=0;r<4;r++) acc[i][j][r]=0.f;

    const bool doA = tid < 256;
    const size_t aoff = (size_t)(bm + ((tid & 255)>>1))*K + (tid&1)*8;
    const size_t boff = (size_t)(bn + (tid>>1))*K + (tid&1)*8;
    const int stoA = ((tid & 255)>>1)*24 + (tid&1)*8;
    const int stoB = 6144 + (tid>>1)*24 + (tid&1)*8;

    unsigned base = (unsigned)__cvta_generic_to_shared(sm);
    const int arow = wm*64 + (lane&15);
    const int acol = (lane>>4)*8;
    const int brow = wn*32 + ((lane>>4)&1)*8 + (lane&7);
    const int bcol = ((lane>>3)&1)*8;
    const int nk = K >> 4;

    {
        uint4 rAh, rAl;
        if (doA) { rAh = *(const uint4*)(Ah + aoff); rAl = *(const uint4*)(Al + aoff); }
        uint4 rBh = *(const uint4*)(Bh + boff);
        uint4 rBl = *(const uint4*)(Bl + boff);
        if (doA) {
            *(uint4*)(sm + stoA) = rAh;
            *(uint4*)(sm + 3072 + stoA) = rAl;
        }
        *(uint4*)(sm + stoB) = rBh;
        *(uint4*)(sm + 6144 + stoB) = rBl;
    }
    __syncthreads();

    for (int kt = 0; kt < nk; ++kt) {
        const int cur = kt & 1;
        const unsigned sb = base + (unsigned)cur*(G2_STG*2);
        uint4 nAh, nAl, nBh, nBl;
        const bool more = (kt + 1 < nk);
        if (more) {
            const size_t kb = boff + (size_t)(kt+1)*16;
            nBh = *(const uint4*)(Bh + kb);
            nBl = *(const uint4*)(Bl + kb);
            if (doA) {
                const size_t ka = aoff + (size_t)(kt+1)*16;
                nAh = *(const uint4*)(Ah + ka);
                nAl = *(const uint4*)(Al + ka);
            }
        }
        unsigned bh[4][2], bl[4][2];
        #pragma unroll
        for (int ng = 0; ng < 2; ++ng) {
            unsigned r4[4];
            ldsm4(r4, sb + 2u*(6144 + (brow + ng*16)*24 + bcol));
            bh[2*ng][0]=r4[0]; bh[2*ng][1]=r4[1]; bh[2*ng+1][0]=r4[2]; bh[2*ng+1][1]=r4[3];
            ldsm4(r4, sb + 2u*(12288 + (brow + ng*16)*24 + bcol));
            bl[2*ng][0]=r4[0]; bl[2*ng][1]=r4[1]; bl[2*ng+1][0]=r4[2]; bl[2*ng+1][1]=r4[3];
        }
        #pragma unroll
        for (int mt = 0; mt < 4; ++mt) {
            unsigned ah[4], al[4];
            ldsm4(ah, sb + 2u*((arow + mt*16)*24 + acol));
            ldsm4(al, sb + 2u*(3072 + (arow + mt*16)*24 + acol));
            #pragma unroll
            for (int nt = 0; nt < 4; ++nt) {
                mma16816(acc[mt][nt], ah, bh[nt]);
                mma16816(acc[mt][nt], ah, bl[nt]);
                mma16816(acc[mt][nt], al, bh[nt]);
            }
        }
        if (more) {
            __nv_bfloat16* d = sm + (cur^1)*G2_STG;
            if (doA) {
                *(uint4*)(d + stoA) = nAh;
                *(uint4*)(d + 3072 + stoA) = nAl;
            }
            *(uint4*)(d + stoB) = nBh;
            *(uint4*)(d + 6144 + stoB) = nBl;
            __syncthreads();
        }
    }
    const int g = lane>>2, tig = lane&3;
    if (MODE == 0) {
        #pragma unroll
        for (int mt = 0; mt < 4; ++mt) {
            const int row0 = bm + wm*64 + mt*16 + g;
            #pragma unroll
            for (int nt = 0; nt < 4; ++nt) {
                const int col = bn + wn*32 + nt*8 + tig*2;
                *(float2*)(C + (size_t)row0*N + col)     = make_float2(acc[mt][nt][0], acc[mt][nt][1]);
                *(float2*)(C + (size_t)(row0+8)*N + col) = make_float2(acc[mt][nt][2], acc[mt][nt][3]);
            }
        }
    } else {
        __syncthreads();
        float* slog = (float*)sm;
        #pragma unroll
        for (int mt = 0; mt < 4; ++mt) {
            #pragma unroll
            for (int half = 0; half < 2; ++half) {
                float pj[4] = {0.f, 0.f, 0.f, 0.f};
                const int rowL = wm*64 + mt*16 + g + half*8;
                #pragma unroll
                for (int nt = 0; nt < 4; ++nt) {
                    #pragma unroll
                    for (int rr = 0; rr < 2; ++rr) {
                        const int col = bn + wn*32 + nt*8 + tig*2 + rr;
                        const float v = geluf(acc[mt][nt][half*2+rr] + bias[col]);
                        #pragma unroll
                        for (int j = 0; j < 4; ++j)
                            pj[j] += v * W2[j*GHID + col];
                    }
                }
                #pragma unroll
                for (int j = 0; j < 4; ++j) {
                    float s = pj[j];
                    s += __shfl_xor_sync(0xffffffffu, s, 1);
                    s += __shfl_xor_sync(0xffffffffu, s, 2);
                    if (tig == 0) slog[wn*512 + rowL*4 + j] = s;
                }
            }
        }
        __syncthreads();
        if (tid < 512) {
            const int row = tid >> 2;
            float s = 0.f;
            #pragma unroll
            for (int w8 = 0; w8 < 8; ++w8) s += slog[w8*512 + tid];
            PLG[((size_t)blockIdx.x*BL + bm + row)*4 + (tid & 3)] = s;
        }
    }
}

// ---------------- conv + silu + l2norm, 8 rows/block, two-pass 32KB smem ----------
#define CV_SMEM ((8192 + 64)*4)
__global__ void __launch_bounds__(256, 4) conv_silu_norm(const float* __restrict__ XQKV,
                               const float* __restrict__ WQ, const float* __restrict__ WK,
                               const float* __restrict__ WV,
                               float* __restrict__ Qo, float* __restrict__ Ko,
                               float* __restrict__ Vo)
{
    extern __shared__ float cs[];
    float* sb = cs;            // [8][1024] shared between Q and K passes
    float* red = cs + 8192;
    const int blk = blockIdx.x;
    const int b = blk / (Ll/8);
    const int l0 = (blk % (Ll/8)) * 8;
    const int tid = threadIdx.x;
    const int warp = tid>>5, lane = tid&31;

    // ---- V pass (direct store, no normalization) ----
    #pragma unroll
    for (int j = 0; j < 4; ++j) {
        const int c = tid + 256*j;
        float win[11];
        #pragma unroll
        for (int t = 0; t < 11; ++t) {
            const int l = l0 - 3 + t;
            win[t] = (l >= 0) ? XQKV[((size_t)(b*Ll + l))*3072 + 2048 + c] : 0.f;
        }
        const float w0 = WV[c*4+0], w1 = WV[c*4+1], w2 = WV[c*4+2], w3 = WV[c*4+3];
        #pragma unroll
        for (int r = 0; r < 8; ++r)
            Vo[((size_t)(b*Ll + l0 + r))*HD + c] =
                siluf(win[r]*w0 + win[r+1]*w1 + win[r+2]*w2 + win[r+3]*w3);
    }

    // ---- two normalized passes: 0 = Q, 1 = K ----
    #pragma unroll
    for (int pass = 0; pass < 2; ++pass) {
        const float* W = pass ? WK : WQ;
        const int plane = pass ? 1024 : 0;
        float* OUT = pass ? Ko : Qo;

        #pragma unroll
        for (int j = 0; j < 4; ++j) {
            const int c = tid + 256*j;
            float win[11];
            #pragma unroll
            for (int t = 0; t < 11; ++t) {
                const int l = l0 - 3 + t;
                win[t] = (l >= 0) ? XQKV[((size_t)(b*Ll + l))*3072 + plane + c] : 0.f;
            }
            const float w0 = W[c*4+0], w1 = W[c*4+1], w2 = W[c*4+2], w3 = W[c*4+3];
            #pragma unroll
            for (int r = 0; r < 8; ++r)
                sb[r*1024 + c] = siluf(win[r]*w0 + win[r+1]*w1 + win[r+2]*w2 + win[r+3]*w3);
        }
        __syncthreads();

        #pragma unroll
        for (int gi = 0; gi < 4; ++gi) {
            const int group = warp*4 + gi;
            const int r = group >> 2, h = group & 3;
            float s = 0.f;
            #pragma unroll
            for (int i = 0; i < 8; ++i) {
                const float v = sb[r*1024 + h*256 + lane + 32*i];
                s += v*v;
            }
            #pragma unroll
            for (int o = 16; o; o >>= 1) s += __shfl_xor_sync(0xffffffff, s, o);
            if (lane == 0) red[group] = rsqrtf(s + 1e-12f);
        }
        __syncthreads();

        #pragma unroll
        for (int j = 0; j < 4; ++j) {
            const int c = tid + 256*j;
            #pragma unroll
            for (int r = 0; r < 8; ++r)
                OUT[((size_t)(b*Ll + l0 + r))*HD + c] = sb[r*1024 + c] * red[r*4 + j];
        }
        __syncthreads();
    }
}

// ---------------- precompute (tensor-core, beta folded into Tinv; 2 CTAs/SM) ---------
#define OQH 0
#define OQL 16896
#define OKH 33792
#define OKL 50688
#define OVH 67584
#define OVL 84480
#define OTH 101376
#define OTL 103936
#define OAM 106496
#define OTI 110720
#define OSB 114944
#define PRE_SMEM 115072

__global__ void __launch_bounds__(256) precompute_kernel(
    const float* __restrict__ Qn, const float* __restrict__ Kn,
    const float* __restrict__ V,  const float* __restrict__ beta,
    float* __restrict__ U,
    __nv_bfloat16* __restrict__ QH, __nv_bfloat16* __restrict__ QL,
    __nv_bfloat16* __restrict__ WH, __nv_bfloat16* __restrict__ WL,
    __nv_bfloat16* __restrict__ KH, __nv_bfloat16* __restrict__ KL,
    __nv_bfloat16* __restrict__ AH, __nv_bfloat16* __restrict__ AL)
{
    extern __shared__ char smraw[];
    const unsigned smb = (unsigned)__cvta_generic_to_shared(smraw);
    float* Amp = (float*)(smraw + OAM);
    float* Tip = (float*)(smraw + OTI);
    float* sbp = (float*)(smraw + OSB);
    const int idx = blockIdx.x;
    const int bh = idx >> 7, ci = idx & 127;
    const int b = bh >> 2, h = bh & 3;
    const int tid = threadIdx.x, warp = tid>>5, lane = tid&31;
    const int g = lane>>2, qp = (lane&3)*2;
    const size_t cb8 = (size_t)idx*8192;
    const size_t cb1 = (size_t)idx*1024;

    if (tid < 32) sbp[tid] = beta[(size_t)(b*Ll + ci*CSs + tid)*4 + h];
    __syncthreads();

    for (int e = tid; e < 8192; e += 256) {
        const int i = e >> 8, d = e & 255;
        const size_t gg = ((size_t)(b*Ll + ci*CSs + i))*HD + h*256 + d;
        const float qv = Qn[gg], kv = Kn[gg], vv = V[gg];
        __nv_bfloat16 hh, ll;
        split1(qv, hh, ll);
        *(__nv_bfloat16*)(smraw + OQH + (i*264+d)*2) = hh;
        *(__nv_bfloat16*)(smraw + OQL + (i*264+d)*2) = ll;
        QH[cb8+e] = hh; QL[cb8+e] = ll;
        split1(kv, hh, ll);
        *(__nv_bfloat16*)(smraw + OKH + (i*264+d)*2) = hh;
        *(__nv_bfloat16*)(smraw + OKL + (i*264+d)*2) = ll;
        split1(vv, hh, ll);
        *(__nv_bfloat16*)(smraw + OVH + (i*264+d)*2) = hh;
        *(__nv_bfloat16*)(smraw + OVL + (i*264+d)*2) = ll;
    }
    __syncthreads();

    {
        const int mt = warp>>2, ntw = warp&3;
        float qk[4] = {0,0,0,0}, kk[4] = {0,0,0,0};
        const unsigned arow_off = (mt*16 + (lane&15))*528 + ((lane>>4)*8)*2;
        const unsigned brow_off = (ntw*8 + (lane&7))*528 + (((lane>>3)&1)*8)*2;
        #pragma unroll
        for (int kt = 0; kt < 16; ++kt) {
            const unsigned kb2 = kt*32;
            unsigned aq[4], aql[4], ak4[4], akl[4], b2h[2], b2l[2];
            ldsm4(aq,  smb + OQH + arow_off + kb2);
            ldsm4(aql, smb + OQL + arow_off + kb2);
            ldsm4(ak4, smb + OKH + arow_off + kb2);
            ldsm4(akl, smb + OKL + arow_off + kb2);
            ldsm2(b2h, smb + OKH + brow_off + kb2);
            ldsm2(b2l, smb + OKL + brow_off + kb2);
            mma16816(qk, aq, b2h);  mma16816(qk, aql, b2h); mma16816(qk, aq, b2l);
            mma16816(kk, ak4, b2h); mma16816(kk, akl, b2h); mma16816(kk, ak4, b2l);
        }
        const int i0 = mt*16 + g, j0 = ntw*8 + qp;
        #pragma unroll
        for (int r = 0; r < 4; ++r) {
            const int i = i0 + (r>>1)*8, j = j0 + (r&1);
            Amp[i*33+j] = (i > j) ? sbp[i]*kk[r] : 0.f;
            const float av = (i >= j) ? qk[r] : 0.f;
            __nv_bfloat16 hh, ll;
            split1(av, hh, ll);
            AH[cb1 + i*32 + j] = hh; AL[cb1 + i*32 + j] = ll;
        }
    }
    for (int e = tid; e < 8192; e += 256) {
        const int d = e >> 5, t = e & 31;
        unsigned short hv = *(unsigned short*)(smraw + OKH + (t*264+d)*2) ^ 0x8000u;
        unsigned short lv = *(unsigned short*)(smraw + OKL + (t*264+d)*2) ^ 0x8000u;
        KH[cb8+e] = *(__nv_bfloat16*)&hv;
        KL[cb8+e] = *(__nv_bfloat16*)&lv;
    }
    __syncthreads();

    if (tid < 32) {
        const int j = tid;
        Tip[j] = (j == 0) ? 1.f : 0.f;
        for (int i2 = 1; i2 < 32; ++i2) {
            __syncwarp();
            float s = 0.f;
            for (int m = 0; m < i2; ++m) s += Amp[i2*33+m]*Tip[m*33+j];
            Tip[i2*33+j] = ((i2 == j) ? 1.f : 0.f) - s;
        }
    }
    __syncthreads();
    for (int e = tid; e < 1024; e += 256) {
        const int i = e >> 5, j = e & 31;
        __nv_bfloat16 hh, ll;
        split1(Tip[i*33+j] * sbp[j], hh, ll);
        *(__nv_bfloat16*)(smraw + OTH + (i*40+j)*2) = hh;
        *(__nv_bfloat16*)(smraw + OTL + (i*40+j)*2) = ll;
    }
    __syncthreads();

    {
        const int mt = warp>>2;
        unsigned TiH[2][4], TiL[2][4];
        #pragma unroll
        for (int kt = 0; kt < 2; ++kt) {
            const unsigned ao = (mt*16 + (lane&15))*80 + (kt*16 + (lane>>4)*8)*2;
            ldsm4(TiH[kt], smb + OTH + ao);
            ldsm4(TiL[kt], smb + OTL + ao);
        }
        const int i0 = mt*16 + g;
        #pragma unroll
        for (int ng = 0; ng < 4; ++ng) {
            const int n0 = (warp&3)*64 + ng*16;
            float aU[2][4], aW[2][4];
            #pragma unroll
            for (int t2 = 0; t2 < 2; ++t2)
                #pragma unroll
                for (int r = 0; r < 4; ++r) { aU[t2][r]=0.f; aW[t2][r]=0.f; }
            #pragma unroll
            for (int kt = 0; kt < 2; ++kt) {
                const unsigned brow = kt*16 + (lane&7) + ((lane>>3)&1)*8;
                const unsigned bcol = n0 + ((lane>>4)&1)*8;
                const unsigned bo = brow*528 + bcol*2;
                unsigned bvh[4], bvl[4], bbh[4], bbl[4];
                ldsm4t(bvh, smb + OVH + bo);
                ldsm4t(bvl, smb + OVL + bo);
                ldsm4t(bbh, smb + OKH + bo);
                ldsm4t(bbl, smb + OKL + bo);
                #pragma unroll
                for (int nt = 0; nt < 2; ++nt) {
                    mma16816(aU[nt], TiH[kt], bvh+2*nt);
                    mma16816(aU[nt], TiL[kt], bvh+2*nt);
                    mma16816(aU[nt], TiH[kt], bvl+2*nt);
                    mma16816(aW[nt], TiH[kt], bbh+2*nt);
                    mma16816(aW[nt], TiL[kt], bbh+2*nt);
                    mma16816(aW[nt], TiH[kt], bbl+2*nt);
                }
            }
            #pragma unroll
            for (int nt = 0; nt < 2; ++nt)
                #pragma unroll
                for (int r = 0; r < 4; ++r) {
                    const int i = i0 + (r>>1)*8;
                    const int d = n0 + nt*8 + qp + (r&1);
                    U[cb8 + i*256 + d] = aU[nt][r];
                    __nv_bfloat16 hh, ll;
                    split1(aW[nt][r], hh, ll);
                    WH[cb8 + i*256 + d] = hh;
                    WL[cb8 + i*256 + d] = ll;
                }
        }
    }
}

// ---------------- tensor-core delta scan (R13 schedule) ----------------
#define STGSZ  72704
#define OFF_KT 145408
#define OFF_UB 210944
#define SC_SMEM 227840

__global__ void __launch_bounds__(128) scan_mma(
    const __nv_bfloat16* __restrict__ QHp, const __nv_bfloat16* __restrict__ QLp,
    const __nv_bfloat16* __restrict__ WHp, const __nv_bfloat16* __restrict__ WLp,
    const __nv_bfloat16* __restrict__ KHp, const __nv_bfloat16* __restrict__ KLp,
    const __nv_bfloat16* __restrict__ AHp, const __nv_bfloat16* __restrict__ ALp,
    const float* __restrict__ Ug, float* __restrict__ Out)
{
    extern __shared__ char smraw[];
    const unsigned smb = (unsigned)__cvta_generic_to_shared(smraw);
    float* ub = (float*)(smraw + OFF_UB);
    const int tid = threadIdx.x, warp = tid>>5, lane = tid&31;
    const int bh = blockIdx.x>>4, cb = blockIdx.x&15;
    const int b = bh>>2, h = bh&3;
    const int g = lane>>2, qp = (lane&3)*2;
    const int brow16 = ((lane>>4)&1)*8 + (lane&7);
    const int bcol8 = ((lane>>3)&1)*8;

    float P[8][4];
    #pragma unroll
    for (int i=0;i<8;++i)
        #pragma unroll
        for (int r=0;r<4;++r) P[i][r]=0.f;

    auto issue = [&](int ci, int stg){
        const size_t b8 = (size_t)(bh*NCc + ci)*8192;
        const size_t b1 = (size_t)(bh*NCc + ci)*1024;
        const unsigned sb = smb + stg*STGSZ;
        const __nv_bfloat16* srcs[4] = {QHp+b8, QLp+b8, WHp+b8, WLp+b8};
        #pragma unroll
        for (int pl = 0; pl < 4; ++pl){
            const unsigned dsb = sb + pl*16384;
            for (int e = tid; e < 1024; e += 128){
                int row = e>>5, c = e&31;
                cpa16(dsb + row*512 + ((c^(row&7))<<4), srcs[pl] + row*256 + c*8);
            }
        }
        const unsigned kb2 = smb + OFF_KT + stg*32768;
        for (int e = tid; e < 1024; e += 128){
            int row = e>>2, c = e&3;
            cpa16(kb2 + row*64 + c*16, KHp + b8 + row*32 + c*8);
            cpa16(kb2 + 16384 + row*64 + c*16, KLp + b8 + row*32 + c*8);
        }
        {
            int row = tid>>2, c = tid&3;
            cpa16(sb + 65536 + row*80 + c*16, AHp + b1 + row*32 + c*8);
            cpa16(sb + 68096 + row*80 + c*16, ALp + b1 + row*32 + c*8);
            cpa16(sb + 70656 + row*64 + c*16, Ug + b8 + (size_t)row*256 + cb*16 + c*4);
        }
    };

    issue(0, 0); CP_COMMIT();

    for (int ci = 0; ci < NCc; ++ci) {
        const int stg = ci & 1;
        const unsigned sb = smb + stg*STGSZ;
        const unsigned kb = smb + OFF_KT + stg*32768;
        CP_WAIT0();
        __syncthreads();

        float accW[4][4], accQ[4][4];
        #pragma unroll
        for (int i=0;i<4;++i)
            #pragma unroll
            for (int r=0;r<4;++r){ accW[i][r]=0.f; accQ[i][r]=0.f; }
        #pragma unroll
        for (int kt = 0; kt < 4; ++kt) {
            unsigned Ah[4], Al[4];
            const float* p0 = P[2*kt]; const float* p1 = P[2*kt+1];
            Ah[0]=pack2(p0[0],p0[1]); Ah[1]=pack2(p0[2],p0[3]);
            Ah[2]=pack2(p1[0],p1[1]); Ah[3]=pack2(p1[2],p1[3]);
            Al[0]=pack2(res1(p0[0]),res1(p0[1])); Al[1]=pack2(res1(p0[2]),res1(p0[3]));
            Al[2]=pack2(res1(p1[0]),res1(p1[1])); Al[3]=pack2(res1(p1[2]),res1(p1[3]));
            const int dcol = warp*64 + kt*16 + bcol8;
            unsigned bwh[4][2], bwl[4][2], bqh[4][2], bql[4][2];
            #pragma unroll
            for (int ng = 0; ng < 2; ++ng) {
                const int row = ng*16 + brow16;
                const unsigned off = row*512 + ((((unsigned)(dcol>>3))^(row&7))<<4);
                unsigned r4[4];
                ldsm4(r4, sb + 32768 + off);
                bwh[2*ng][0]=r4[0]; bwh[2*ng][1]=r4[1]; bwh[2*ng+1][0]=r4[2]; bwh[2*ng+1][1]=r4[3];
                ldsm4(r4, sb + 49152 + off);
                bwl[2*ng][0]=r4[0]; bwl[2*ng][1]=r4[1]; bwl[2*ng+1][0]=r4[2]; bwl[2*ng+1][1]=r4[3];
                ldsm4(r4, sb + off);
                bqh[2*ng][0]=r4[0]; bqh[2*ng][1]=r4[1]; bqh[2*ng+1][0]=r4[2]; bqh[2*ng+1][1]=r4[3];
                ldsm4(r4, sb + 16384 + off);
                bql[2*ng][0]=r4[0]; bql[2*ng][1]=r4[1]; bql[2*ng+1][0]=r4[2]; bql[2*ng+1][1]=r4[3];
            }
            #pragma unroll
            for (int nt = 0; nt < 4; ++nt) {
                mma16816(accW[nt], Ah, bwh[nt]);
                mma16816(accW[nt], Al, bwh[nt]);
                mma16816(accW[nt], Ah, bwl[nt]);
                mma16816(accQ[nt], Ah, bqh[nt]);
                mma16816(accQ[nt], Al, bqh[nt]);
                mma16816(accQ[nt], Ah, bql[nt]);
            }
        }
        #pragma unroll
        for (int nt = 0; nt < 4; ++nt)
            #pragma unroll
            for (int r = 0; r < 4; ++r) {
                int c = g + ((r>>1)<<3), t = nt*8 + qp + (r&1);
                ub[(c*4+warp)*66 + t] = accW[nt][r];
                ub[(c*4+warp)*66 + 32 + t] = accQ[nt][r];
            }
        if (ci + 1 < NCc) { issue(ci+1, stg^1); CP_COMMIT(); }
        __syncthreads();

        const float* su = (const float*)(smraw + stg*STGSZ + 70656);
        unsigned UH[2][4], UL[2][4];
        #pragma unroll
        for (int kt = 0; kt < 2; ++kt) {
            float v[8];
            #pragma unroll
            for (int p = 0; p < 8; ++p) {
                const int c = g + (((p>>1)&1)<<3);
                const int t = kt*16 + qp + (p&1) + ((p>>2)<<3);
                const int bi = (c*4)*66 + t;
                v[p] = su[t*16 + c] + ub[bi] + ub[bi+66] + ub[bi+132] + ub[bi+198];
            }
            UH[kt][0]=pack2(v[0],v[1]); UH[kt][1]=pack2(v[2],v[3]);
            UH[kt][2]=pack2(v[4],v[5]); UH[kt][3]=pack2(v[6],v[7]);
            UL[kt][0]=pack2(res1(v[0]),res1(v[1])); UL[kt][1]=pack2(res1(v[2]),res1(v[3]));
            UL[kt][2]=pack2(res1(v[4]),res1(v[5])); UL[kt][3]=pack2(res1(v[6]),res1(v[7]));
        }
        float oc[4];
        const int i0 = warp*8 + qp;
        #pragma unroll
        for (int r = 0; r < 4; ++r) {
            const int c = g + ((r>>1)<<3);
            const int bi = (c*4)*66 + 32 + i0 + (r&1);
            oc[r] = -(ub[bi] + ub[bi+66] + ub[bi+132] + ub[bi+198]);
        }

        #pragma unroll
        for (int kt = 0; kt < 2; ++kt) {
            unsigned bh2[2], bl2[2];
            const unsigned aoff = (warp*8 + (lane&7))*80 + (kt*16 + bcol8)*2;
            ldsm2(bh2, sb + 65536 + aoff);
            ldsm2(bl2, sb + 68096 + aoff);
            mma16816(oc, UH[kt], bh2);
            mma16816(oc, UL[kt], bh2);
            mma16816(oc, UH[kt], bl2);
        }
        {
            const size_t base = ((size_t)(b*Ll + ci*CSs + i0))*HD + h*256 + cb*16;
            Out[base + g]          = oc[0];
            Out[base + HD + g]     = oc[1];
            Out[base + g + 8]      = oc[2];
            Out[base + HD + g + 8] = oc[3];
        }

        #pragma unroll
        for (int kt = 0; kt < 2; ++kt) {
            #pragma unroll
            for (int np = 0; np < 4; ++np) {
                unsigned bh4[4], bl4[4];
                const unsigned off = (warp*64 + np*16 + brow16)*64 + (kt*16 + bcol8)*2;
                ldsm4(bh4, kb + off);
                ldsm4(bl4, kb + 16384 + off);
                mma16816(P[2*np],   UH[kt], bh4);
                mma16816(P[2*np],   UL[kt], bh4);
                mma16816(P[2*np],   UH[kt], bl4);
                mma16816(P[2*np+1], UH[kt], bh4+2);
                mma16816(P[2*np+1], UL[kt], bh4+2);
                mma16816(P[2*np+1], UH[kt], bl4+2);
            }
        }
    }
}

// ---------------- FIR short/long + gate_in, 16 rows/block ----------
__global__ void __launch_bounds__(256) fir_gatein_kernel(
                                  const unsigned* __restrict__ hsHu, const unsigned* __restrict__ hsLu,
                                  const float* __restrict__ V,
                                  const float* __restrict__ ws, const float* __restrict__ wl,
                                  const float* __restrict__ Dl,
                                  float* __restrict__ Sout, float* __restrict__ Lout,
                                  __nv_bfloat16* __restrict__ GinH, __nv_bfloat16* __restrict__ GinL)
{
    const int blk = blockIdx.x;
    const int b = blk / (Ll/16);
    const int l0 = (blk % (Ll/16)) * 16;
    const int tid = threadIdx.x;
    float smean[16], lmean[16], dmean[16];
    #pragma unroll
    for (int r = 0; r < 16; ++r) { smean[r]=0.f; lmean[r]=0.f; dmean[r]=0.f; }
    for (int j = 0; j < 4; ++j) {
        const int ch = tid + 256*j;
        float win[46];
        #pragma unroll
        for (int t = 0; t < 46; ++t) {
            const int l = l0 - 30 + t;
            win[t] = (l >= 0) ? V[((size_t)(b*Ll + l))*HD + ch] : 0.f;
        }
        float wlr[31];
        #pragma unroll
        for (int t = 0; t < 31; ++t) wlr[t] = wl[ch*31 + t];
        const float w0 = ws[ch*3+0], w1 = ws[ch*3+1], w2 = ws[ch*3+2];
        #pragma unroll
        for (int r = 0; r < 16; ++r) {
            float yl = 0.f;
            #pragma unroll
            for (int t = 0; t < 31; ++t) yl += win[r+t]*wlr[t];
            const float ysv = win[r+28]*w0 + win[r+29]*w1 + win[r+30]*w2;
            const size_t row = (size_t)(b*Ll + l0 + r);
            Sout[row*HD + ch] = ysv;
            Lout[row*HD + ch] = yl;
            smean[r] += ysv; lmean[r] += yl;
            dmean[r] += Dl[row*HD + ch];
        }
    }
    for (int r = 0; r < 16; ++r) {
        const size_t row = (size_t)(b*Ll + l0 + r);
        __nv_bfloat16* gH = GinH + row*GIN;
        __nv_bfloat16* gL = GinL + row*GIN;
        #pragma unroll
        for (int j = 0; j < 2; ++j) {
            const int e = tid + 256*j;
            ((unsigned*)gH)[e] = hsHu[row*512 + e];
            ((unsigned*)gL)[e] = hsLu[row*512 + e];
        }
        __nv_bfloat16 hh, ll;
        split1(smean[r]*0.25f, hh, ll);
        gH[1024 + tid] = hh; gL[1024 + tid] = ll;
        split1(lmean[r]*0.25f, hh, ll);
        gH[1280 + tid] = hh; gL[1280 + tid] = ll;
        split1(dmean[r]*0.25f, hh, ll);
        gH[1536 + tid] = hh; gL[1536 + tid] = ll;
    }
}

// ---------------- combine + gate softmax + RMSNorm ----------------
__global__ void combine_kernel(const float* __restrict__ Sh, const float* __restrict__ Lg,
                               const float* __restrict__ Dl, const float* __restrict__ V,
                               const float* __restrict__ PLG, const float* __restrict__ b2,
                               const float* __restrict__ ltemp, const float* __restrict__ onw,
                               __nv_bfloat16* __restrict__ OH, __nv_bfloat16* __restrict__ OL)
{
    const int row = blockIdx.x;
    const int tid = threadIdx.x, lane = tid & 31;
    __shared__ float red[4];
    __shared__ float sw[4];
    if (tid == 0) {
        const float t = log1pf(expf(ltemp[0])) + 1e-4f;
        float lg[4];
        #pragma unroll
        for (int j = 0; j < 4; ++j)
            lg[j] = PLG[(size_t)row*4 + j] + PLG[((size_t)BL + row)*4 + j]
                  + PLG[((size_t)2*BL + row)*4 + j] + PLG[((size_t)3*BL + row)*4 + j] + b2[j];
        float m = fmaxf(fmaxf(lg[0], lg[1]), fmaxf(lg[2], lg[3]));
        float e[4]; float se = 0.f;
        #pragma unroll
        for (int j = 0; j < 4; ++j) { e[j] = expf((lg[j]-m)/t); se += e[j]; }
        #pragma unroll
        for (int j = 0; j < 4; ++j) e[j] /= se;
        const float fl = 0.05f * e[3];
        e[0] = fmaxf(e[0], fl);
        e[1] = fmaxf(e[1], fl);
        const float s2 = e[0]+e[1]+e[2]+e[3];
        #pragma unroll
        for (int j = 0; j < 4; ++j) sw[j] = e[j]/s2;
    }
    if (tid < 4) red[tid] = 0.f;
    __syncthreads();
    const float w0 = sw[0], w1 = sw[1], w2 = sw[2], w3 = sw[3];
    float ov[4];
    #pragma unroll
    for (int j = 0; j < 4; ++j) {
        const size_t g = (size_t)row*HD + tid + 256*j;
        ov[j] = w0*Sh[g] + w1*Lg[g] + w2*Dl[g] + w3*V[g];
        float v = ov[j]*ov[j];
        #pragma unroll
        for (int o = 16; o; o >>= 1) v += __shfl_xor_sync(0xffffffff, v, o);
        if (lane == 0) atomicAdd(&red[j], v);
    }
    __syncthreads();
    #pragma unroll
    for (int j = 0; j < 4; ++j) {
        const float sc = rsqrtf(red[j]*(1.f/256.f) + 1e-5f) * onw[tid];
        __nv_bfloat16 hh, ll;
        split1(ov[j]*sc, hh, ll);
        OH[(size_t)row*HD + tid + 256*j] = hh;
        OL[(size_t)row*HD + tid + 256*j] = ll;
    }
}

// ---------------- launch ----------------
extern "C" void kernel_launch(void* const* d_in, const int* in_sizes, int n_in,
                              void* d_out, int out_size)
{
    const float* hs  = (const float*)d_in[0];
    const float* qw  = (const float*)d_in[1];
    const float* kw  = (const float*)d_in[2];
    const float* vw  = (const float*)d_in[3];
    const float* bw  = (const float*)d_in[4];
    const float* qcw = (const float*)d_in[5];
    const float* kcw = (const float*)d_in[6];
    const float* vcw = (const float*)d_in[7];
    const float* fsw = (const float*)d_in[8];
    const float* flw = (const float*)d_in[9];
    const float* w1  = (const float*)d_in[10];
    const float* b1  = (const float*)d_in[11];
    const float* w2  = (const float*)d_in[12];
    const float* b2  = (const float*)d_in[13];
    const float* lt  = (const float*)d_in[14];
    const float* onw = (const float*)d_in[15];
    const float* ow  = (const float*)d_in[16];
    float* out = (float*)d_out;

    float *xqkv,*q,*k,*v,*u,*delta,*shrt,*lng,*plg,*beta;
    __nv_bfloat16 *hsH,*hsL,*ginH,*ginL,*ocH,*ocL,*wtH,*wtL;
    __nv_bfloat16 *qh,*ql,*wh,*wlp,*kh,*kl,*ah,*al;
    cudaGetSymbolAddress((void**)&xqkv, g_xqkv);
    cudaGetSymbolAddress((void**)&q,    g_q);
    cudaGetSymbolAddress((void**)&k,    g_k);
    cudaGetSymbolAddress((void**)&v,    g_v);
    cudaGetSymbolAddress((void**)&u,    g_u);
    cudaGetSymbolAddress((void**)&delta,g_delta);
    cudaGetSymbolAddress((void**)&shrt, g_short);
    cudaGetSymbolAddress((void**)&lng,  g_long);
    cudaGetSymbolAddress((void**)&plg,  g_plg);
    cudaGetSymbolAddress((void**)&beta, g_beta);
    cudaGetSymbolAddress((void**)&hsH,  g_hsH);
    cudaGetSymbolAddress((void**)&hsL,  g_hsL);
    cudaGetSymbolAddress((void**)&ginH, g_ginH);
    cudaGetSymbolAddress((void**)&ginL, g_ginL);
    cudaGetSymbolAddress((void**)&ocH,  g_ocH);
    cudaGetSymbolAddress((void**)&ocL,  g_ocL);
    cudaGetSymbolAddress((void**)&wtH,  g_wtH);
    cudaGetSymbolAddress((void**)&wtL,  g_wtL);
    cudaGetSymbolAddress((void**)&qh,   g_qh);
    cudaGetSymbolAddress((void**)&ql,   g_ql);
    cudaGetSymbolAddress((void**)&wh,   g_wh);
    cudaGetSymbolAddress((void**)&wlp,  g_wl);
    cudaGetSymbolAddress((void**)&kh,   g_kh);
    cudaGetSymbolAddress((void**)&kl,   g_kl);
    cudaGetSymbolAddress((void**)&ah,   g_ah);
    cudaGetSymbolAddress((void**)&al,   g_al);

    cudaFuncSetAttribute(precompute_kernel, cudaFuncAttributeMaxDynamicSharedMemorySize, PRE_SMEM);
    cudaFuncSetAttribute(scan_mma, cudaFuncAttributeMaxDynamicSharedMemorySize, SC_SMEM);
    cudaFuncSetAttribute(hgemm_nt<0>, cudaFuncAttributeMaxDynamicSharedMemorySize, G2_SMEM);
    cudaFuncSetAttribute(hgemm_nt<2>, cudaFuncAttributeMaxDynamicSharedMemorySize, G2_SMEM);
    cudaFuncSetAttribute(conv_silu_norm,  cudaFuncAttributeMaxDynamicSharedMemorySize, CV_SMEM);

    split_hs_beta<<<BL, 256>>>((const float4*)hs, (uint2*)hsH, (uint2*)hsL, bw, beta);
    wsplit_kernel<<<(W4_O + 255)/256, 256>>>((const float4*)qw, (const float4*)kw,
                                             (const float4*)vw, (const float4*)w1,
                                             (const float4*)ow, (uint2*)wtH, (uint2*)wtL);

    hgemm_nt<0><<<dim3(3072/256, BL/128), 512, G2_SMEM>>>(
        hsH, hsL, wtH+WOFF_Q, wtL+WOFF_Q, xqkv, BL, 3072, Dd, nullptr, nullptr, nullptr);
    conv_silu_norm<<<BL/8, 256, CV_SMEM>>>(xqkv, qcw, kcw, vcw, q, k, v);
    precompute_kernel<<<8*NCc, 256, PRE_SMEM>>>(q, k, v, beta, u,
                                                qh, ql, wh, wlp, kh, kl, ah, al);
    scan_mma<<<128, 128, SC_SMEM>>>(qh, ql, wh, wlp, kh, kl, ah, al, u, delta);
    fir_gatein_kernel<<<Bb*(Ll/16), 256>>>((const unsigned*)hsH, (const unsigned*)hsL,
                                           v, fsw, flw, delta, shrt, lng, ginH, ginL);
    hgemm_nt<2><<<dim3(GHID/256, BL/128), 512, G2_SMEM>>>(
        ginH, ginL, wtH+WOFF_W1, wtL+WOFF_W1, nullptr, BL, GHID, GIN, b1, w2, plg);
    combine_kernel<<<BL, 256>>>(shrt, lng, delta, v, plg, b2, lt, onw, ocH, ocL);
    hgemm_nt<0><<<dim3(Dd/256, BL/128), 512, G2_SMEM>>>(
        ocH, ocL, wtH+WOFF_O, wtL+WOFF_O, out, BL, Dd, HD, nullptr, nullptr, nullptr);
}